// round 1
// baseline (speedup 1.0000x reference)
#include <cuda_runtime.h>
#include <cuda_bf16.h>
#include <math.h>

// Problem constants
#define BB 64
#define NN 512
#define HH 32
#define EE 4
#define KDIM 2048          // N*E contraction dim
#define NSTEPS 5

// ---------------------------------------------------------------------------
// Scratch (static __device__ arrays; no allocations allowed)
// ---------------------------------------------------------------------------
__device__ float g_Sin [ (size_t)BB * KDIM * HH ];   // 16 MB  (B, 2048, 32) reordered
__device__ float g_Sout[ (size_t)BB * KDIM * HH ];   // 16 MB
__device__ float g_ain [ (size_t)BB * NN * HH ];     // 4 MB   (B, 512, 32)
__device__ float g_aout[ (size_t)BB * NN * HH ];     // 4 MB
__device__ float g_h   [ (size_t)BB * NN * HH ];     // 4 MB

// ---------------------------------------------------------------------------
// Kernel 1: S_in/S_out projections + reorder scatter
//   S[b,n,j] = sum_k h[b,n,k]*W[j,k] + bias[j], j = h'*4 + e
//   write S_reord[b, e*512+n, h'] = S[b,n,h'*4+e]
// One warp per token; lane = h' (0..31); each lane computes e=0..3.
// ---------------------------------------------------------------------------
__global__ void __launch_bounds__(512)
s_kernel(const float* __restrict__ h_in,
         const float* __restrict__ W_in,  const float* __restrict__ b_in,
         const float* __restrict__ W_out, const float* __restrict__ b_out)
{
    __shared__ float WiT[32][128];   // [k][j]
    __shared__ float WoT[32][128];
    __shared__ float bi[128];
    __shared__ float bo[128];
    __shared__ float hs[16][32];

    const int tid = threadIdx.x;
    for (int i = tid; i < 128 * 32; i += 512) {
        int j = i >> 5, k = i & 31;
        WiT[k][j] = W_in[i];
        WoT[k][j] = W_out[i];
    }
    if (tid < 128) { bi[tid] = b_in[tid]; bo[tid] = b_out[tid]; }

    const int w    = tid >> 5;
    const int lane = tid & 31;
    const int token = blockIdx.x * 16 + w;
    hs[w][lane] = h_in[(size_t)token * 32 + lane];
    __syncthreads();

    float ai0 = bi[lane*4+0], ai1 = bi[lane*4+1], ai2 = bi[lane*4+2], ai3 = bi[lane*4+3];
    float ao0 = bo[lane*4+0], ao1 = bo[lane*4+1], ao2 = bo[lane*4+2], ao3 = bo[lane*4+3];

    #pragma unroll
    for (int k = 0; k < 32; k++) {
        float hk = hs[w][k];
        float4 wi = *(const float4*)&WiT[k][lane*4];
        float4 wo = *(const float4*)&WoT[k][lane*4];
        ai0 += hk*wi.x; ai1 += hk*wi.y; ai2 += hk*wi.z; ai3 += hk*wi.w;
        ao0 += hk*wo.x; ao1 += hk*wo.y; ao2 += hk*wo.z; ao3 += hk*wo.w;
    }

    const int b = token >> 9;
    const int n = token & 511;
    size_t base = (size_t)b * KDIM * 32;
    g_Sin [base + ((size_t)(0*512 + n))*32 + lane] = ai0;
    g_Sin [base + ((size_t)(1*512 + n))*32 + lane] = ai1;
    g_Sin [base + ((size_t)(2*512 + n))*32 + lane] = ai2;
    g_Sin [base + ((size_t)(3*512 + n))*32 + lane] = ai3;
    g_Sout[base + ((size_t)(0*512 + n))*32 + lane] = ao0;
    g_Sout[base + ((size_t)(1*512 + n))*32 + lane] = ao1;
    g_Sout[base + ((size_t)(2*512 + n))*32 + lane] = ao2;
    g_Sout[base + ((size_t)(3*512 + n))*32 + lane] = ao3;
}

// ---------------------------------------------------------------------------
// Kernel 2: big batched GEMM
//   a[b, n, h] = sum_{M=0..2047} m[b, n, which*2048 + M] * S_reord[b, M, h]
// Block: 256 threads, output tile 256 rows x 32 cols.
// Per-thread: 8 rows (rg + 32*i) x 4 cols (cg*4..+3).
// K staged in smem in chunks of 32.
// ---------------------------------------------------------------------------
__global__ void __launch_bounds__(256)
gemm_kernel(const float* __restrict__ m)
{
    __shared__ float ms[256][36];   // [row][k], stride 36 -> conflict-free, 16B aligned
    __shared__ float ss[32][32];    // [k][col]

    const int b     = blockIdx.z;
    const int which = blockIdx.y;   // 0 = in, 1 = out
    const int nt    = blockIdx.x;   // n tile (0 or 1)

    const float* __restrict__ S =
        (which ? g_Sout : g_Sin) + (size_t)b * KDIM * 32;
    const float* __restrict__ mb =
        m + ((size_t)(b * NN + nt * 256)) * 4096 + (size_t)which * 2048;

    const int tid = threadIdx.x;
    const int cg  = tid & 7;        // col group: cols cg*4 .. cg*4+3
    const int rg  = tid >> 3;       // row group: rows rg + 32*i
    const int lf4 = (tid & 7) * 4;  // float4 column offset for loads
    const int lr  = tid >> 3;       // load row within 32-row pass
    const int sk  = tid >> 3;       // S load row

    float acc[8][4];
    #pragma unroll
    for (int i = 0; i < 8; i++)
        { acc[i][0] = 0.f; acc[i][1] = 0.f; acc[i][2] = 0.f; acc[i][3] = 0.f; }

    for (int c = 0; c < KDIM / 32; c++) {
        const int k0 = c * 32;
        // stage m tile (256 x 32) -- coalesced 128B rows
        #pragma unroll
        for (int p = 0; p < 8; p++) {
            int row = lr + 32 * p;
            *(float4*)&ms[row][lf4] =
                *(const float4*)&mb[(size_t)row * 4096 + k0 + lf4];
        }
        // stage S tile (32 x 32)
        *(float4*)&ss[sk][lf4] =
            *(const float4*)&S[(size_t)(k0 + sk) * 32 + lf4];
        __syncthreads();

        #pragma unroll 8
        for (int k = 0; k < 32; k++) {
            float4 b4 = *(const float4*)&ss[k][cg * 4];
            #pragma unroll
            for (int i = 0; i < 8; i++) {
                float av = ms[rg + 32 * i][k];
                acc[i][0] += av * b4.x;
                acc[i][1] += av * b4.y;
                acc[i][2] += av * b4.z;
                acc[i][3] += av * b4.w;
            }
        }
        __syncthreads();
    }

    float* __restrict__ outp = which ? g_aout : g_ain;
    #pragma unroll
    for (int i = 0; i < 8; i++) {
        int n = nt * 256 + rg + 32 * i;
        float4 v = make_float4(acc[i][0], acc[i][1], acc[i][2], acc[i][3]);
        *(float4*)&outp[((size_t)(b * NN + n)) * 32 + cg * 4] = v;
    }
}

// ---------------------------------------------------------------------------
// Kernel 3: gates (z, r, h_hat, h update). One warp per token; lane = j.
// ---------------------------------------------------------------------------
__device__ __forceinline__ float sigmoidf_(float x) {
    return 1.0f / (1.0f + expf(-x));
}

__global__ void __launch_bounds__(512)
gates_kernel(const float* __restrict__ h_in,
             const float* __restrict__ Wz, const float* __restrict__ bz,
             const float* __restrict__ Wr, const float* __restrict__ br,
             const float* __restrict__ Wt, const float* __restrict__ bt)
{
    __shared__ float Wzs[96][32];   // [k][j]
    __shared__ float Wrs[96][32];
    __shared__ float Wts[96][32];
    __shared__ float cats[16][96];

    const int tid = threadIdx.x;
    for (int i = tid; i < 32 * 96; i += 512) {
        int j = i / 96, k = i % 96;
        Wzs[k][j] = Wz[i];
        Wrs[k][j] = Wr[i];
        Wts[k][j] = Wt[i];
    }

    const int w    = tid >> 5;
    const int lane = tid & 31;
    const int token = blockIdx.x * 16 + w;
    const size_t t32 = (size_t)token * 32;

    cats[w][lane]      = g_ain [t32 + lane];
    cats[w][32 + lane] = g_aout[t32 + lane];
    float hj = h_in[t32 + lane];
    cats[w][64 + lane] = hj;
    __syncthreads();

    float az = __ldg(&bz[lane]);
    float ar = __ldg(&br[lane]);
    float at = __ldg(&bt[lane]);

    #pragma unroll 8
    for (int k = 0; k < 64; k++) {
        float cv = cats[w][k];
        az += cv * Wzs[k][lane];
        ar += cv * Wrs[k][lane];
        at += cv * Wts[k][lane];
    }
    #pragma unroll 8
    for (int k = 64; k < 96; k++) {
        float cv = cats[w][k];
        az += cv * Wzs[k][lane];
        ar += cv * Wrs[k][lane];
    }

    float z = sigmoidf_(az);
    float r = sigmoidf_(ar);

    cats[w][64 + lane] = r * hj;
    __syncwarp();

    #pragma unroll 8
    for (int k = 64; k < 96; k++) {
        at += cats[w][k] * Wts[k][lane];
    }

    float hhat = tanhf(at);
    g_h[t32 + lane] = hj + z * (hhat - hj);   // (1-z)*h + z*hhat
}

// ---------------------------------------------------------------------------
// Kernel 4: final head. out[b,n] = sum_j tanh([h,a]@W1.T+b1)_j * W2_j + b2
// One warp per token.
// ---------------------------------------------------------------------------
__global__ void __launch_bounds__(512)
final_kernel(const float* __restrict__ a,
             const float* __restrict__ W1, const float* __restrict__ b1,
             const float* __restrict__ W2, const float* __restrict__ b2,
             float* __restrict__ out)
{
    __shared__ float W1s[33][32];   // [k][j]
    __shared__ float hs[16][32];

    const int tid = threadIdx.x;
    for (int i = tid; i < 32 * 33; i += 512) {
        int j = i / 33, k = i % 33;
        W1s[k][j] = W1[i];
    }

    const int w    = tid >> 5;
    const int lane = tid & 31;
    const int token = blockIdx.x * 16 + w;
    const size_t t32 = (size_t)token * 32;

    hs[w][lane] = g_h[t32 + lane];
    __syncthreads();

    float acc = __ldg(&b1[lane]);
    #pragma unroll
    for (int k = 0; k < 32; k++) {
        acc += hs[w][k] * W1s[k][lane];
    }
    acc += __ldg(&a[token]) * W1s[32][lane];

    float v = tanhf(acc) * __ldg(&W2[lane]);
    #pragma unroll
    for (int off = 16; off > 0; off >>= 1)
        v += __shfl_down_sync(0xFFFFFFFFu, v, off);

    if (lane == 0)
        out[token] = v + __ldg(&b2[0]);
}

// ---------------------------------------------------------------------------
// Launch
// ---------------------------------------------------------------------------
extern "C" void kernel_launch(void* const* d_in, const int* in_sizes, int n_in,
                              void* d_out, int out_size)
{
    const float* x     = (const float*)d_in[0];
    const float* a     = (const float*)d_in[1];
    const float* m     = (const float*)d_in[2];
    const float* W_in  = (const float*)d_in[3];
    const float* b_in  = (const float*)d_in[4];
    const float* W_out = (const float*)d_in[5];
    const float* b_out = (const float*)d_in[6];
    const float* Wz    = (const float*)d_in[7];
    const float* bz    = (const float*)d_in[8];
    const float* Wr    = (const float*)d_in[9];
    const float* br    = (const float*)d_in[10];
    const float* Wt    = (const float*)d_in[11];
    const float* bt    = (const float*)d_in[12];
    const float* W1    = (const float*)d_in[13];
    const float* b1    = (const float*)d_in[14];
    const float* W2    = (const float*)d_in[15];
    const float* b2    = (const float*)d_in[16];
    float* out = (float*)d_out;

    const int n_tokens = BB * NN;                 // 32768
    const int tok_blocks = n_tokens / 16;         // 2048

    float* g_h_ptr = nullptr;  // only used for h source selection; kernels use symbol

    for (int step = 0; step < NSTEPS; step++) {
        const float* hsrc = nullptr;
        if (step == 0) {
            hsrc = x;
        } else {
            // address of device symbol usable directly inside kernels;
            // here we only need a pointer value valid on device: use
            // cudaGetSymbolAddress once is not graph-friendly per-call ordering,
            // so instead kernels that need g_h take it via this helper trick:
            hsrc = nullptr;  // replaced below
        }
        (void)g_h_ptr;

        if (step == 0) {
            s_kernel<<<tok_blocks, 512>>>(x, W_in, b_in, W_out, b_out);
        } else {
            // get device pointer to g_h (host-side symbol lookup is not a stream op)
            static float* hdev = nullptr;
            if (!hdev) cudaGetSymbolAddress((void**)&hdev, g_h);
            s_kernel<<<tok_blocks, 512>>>(hdev, W_in, b_in, W_out, b_out);
        }

        dim3 ggrid(2, 2, BB);
        gemm_kernel<<<ggrid, 256>>>(m);

        if (step == 0) {
            gates_kernel<<<tok_blocks, 512>>>(x, Wz, bz, Wr, br, Wt, bt);
        } else {
            static float* hdev2 = nullptr;
            if (!hdev2) cudaGetSymbolAddress((void**)&hdev2, g_h);
            gates_kernel<<<tok_blocks, 512>>>(hdev2, Wz, bz, Wr, br, Wt, bt);
        }
    }

    final_kernel<<<tok_blocks, 512>>>(a, W1, b1, W2, b2, out);
}

// round 2
// speedup vs baseline: 1.6185x; 1.6185x over previous
#include <cuda_runtime.h>
#include <cuda_bf16.h>
#include <cuda_pipeline.h>
#include <math.h>

#define BB 64
#define NN 512
#define HH 32
#define EE 4
#define KDIM 2048
#define NSTEPS 5

// ---------------------------------------------------------------------------
// Scratch
// ---------------------------------------------------------------------------
__device__ float g_Sin [ (size_t)BB * KDIM * HH ];   // 16 MB
__device__ float g_Sout[ (size_t)BB * KDIM * HH ];   // 16 MB
__device__ float g_ain [ (size_t)BB * NN * HH ];     // 4 MB
__device__ float g_aout[ (size_t)BB * NN * HH ];     // 4 MB
__device__ float g_h   [ (size_t)BB * NN * HH ];     // 4 MB

// ---------------------------------------------------------------------------
// Kernel 1: S projections + reorder scatter (GEMM-style, 32 tokens/block)
//   S[n,j] = sum_k h[n,k] * W[j,k] + b[j],   j = h'*4 + e
//   S_reord[b, e*512+n, h'] = S[n, h'*4+e]
// 128 threads: lane hp = h' (0..31), rg = tid>>5 (0..3), rows rg+4i (i<8).
// Each thread's 4 cols are j = hp*4+e, e=0..3 -> scatter is coalesced in hp.
// ---------------------------------------------------------------------------
__global__ void __launch_bounds__(128)
s_kernel(const float* __restrict__ h_in,
         const float* __restrict__ W_in,  const float* __restrict__ b_in,
         const float* __restrict__ W_out, const float* __restrict__ b_out,
         float* __restrict__ Sin_, float* __restrict__ Sout_)
{
    __shared__ float hs[32][36];
    __shared__ float wi[32][132];   // [k][j]
    __shared__ float wo[32][132];

    const int tid = threadIdx.x;

    // Load W transposed into smem: wi[k][j] = W_in[j*32+k]
    {
        int jj  = tid >> 3;
        int kf4 = (tid & 7) * 4;
        #pragma unroll
        for (int p = 0; p < 8; p++) {
            int j = jj + 16 * p;
            float4 v = *(const float4*)&W_in [j * 32 + kf4];
            wi[kf4+0][j] = v.x; wi[kf4+1][j] = v.y; wi[kf4+2][j] = v.z; wi[kf4+3][j] = v.w;
            float4 u = *(const float4*)&W_out[j * 32 + kf4];
            wo[kf4+0][j] = u.x; wo[kf4+1][j] = u.y; wo[kf4+2][j] = u.z; wo[kf4+3][j] = u.w;
        }
    }

    const int token0 = blockIdx.x * 32;
    // Load h tile (32 x 32): 8 floats per thread
    {
        int r = tid >> 2;
        int c = (tid & 3) * 8;
        const float* src = &h_in[(size_t)(token0 + r) * 32 + c];
        *(float4*)&hs[r][c]     = *(const float4*)&src[0];
        *(float4*)&hs[r][c + 4] = *(const float4*)&src[4];
    }
    __syncthreads();

    const int hp = tid & 31;
    const int rg = tid >> 5;

    float ai[8][4], ao[8][4];
    float4 bi4 = *(const float4*)&b_in [hp * 4];
    float4 bo4 = *(const float4*)&b_out[hp * 4];
    #pragma unroll
    for (int i = 0; i < 8; i++) {
        ai[i][0] = bi4.x; ai[i][1] = bi4.y; ai[i][2] = bi4.z; ai[i][3] = bi4.w;
        ao[i][0] = bo4.x; ao[i][1] = bo4.y; ao[i][2] = bo4.z; ao[i][3] = bo4.w;
    }

    #pragma unroll 4
    for (int k = 0; k < 32; k++) {
        float4 wv = *(const float4*)&wi[k][hp * 4];
        float4 wu = *(const float4*)&wo[k][hp * 4];
        #pragma unroll
        for (int i = 0; i < 8; i++) {
            float av = hs[rg + 4 * i][k];
            ai[i][0] += av * wv.x; ai[i][1] += av * wv.y;
            ai[i][2] += av * wv.z; ai[i][3] += av * wv.w;
            ao[i][0] += av * wu.x; ao[i][1] += av * wu.y;
            ao[i][2] += av * wu.z; ao[i][3] += av * wu.w;
        }
    }

    const int b     = token0 >> 9;
    const int nbase = token0 & 511;
    const size_t base = (size_t)b * KDIM * 32;
    #pragma unroll
    for (int i = 0; i < 8; i++) {
        int n = nbase + rg + 4 * i;
        #pragma unroll
        for (int e = 0; e < 4; e++) {
            Sin_ [base + (size_t)(e * 512 + n) * 32 + hp] = ai[i][e];
            Sout_[base + (size_t)(e * 512 + n) * 32 + hp] = ao[i][e];
        }
    }
}

// ---------------------------------------------------------------------------
// Kernel 2: big batched GEMM with cp.async double buffering
//   a[b,n,h] = sum_M m[b,n,which*2048+M] * S_reord[b,M,h]
// Grid (4, 2, 64) = 512 blocks, 128 threads, tile 128 rows x 32 cols,
// per-thread 8 rows (rg+16i) x 4 cols (cg*4..+3).
// ---------------------------------------------------------------------------
__device__ __forceinline__ void stage_chunk(
    float (*msb)[36], float (*ssb)[36],
    const float* __restrict__ mb, const float* __restrict__ S,
    int k0, int rg, int lf4)
{
    #pragma unroll
    for (int p = 0; p < 8; p++) {
        int row = rg + 16 * p;
        __pipeline_memcpy_async(&msb[row][lf4],
                                &mb[(size_t)row * 4096 + k0 + lf4], 16);
    }
    #pragma unroll
    for (int q = 0; q < 2; q++) {
        int r = rg + 16 * q;
        __pipeline_memcpy_async(&ssb[r][lf4],
                                &S[(size_t)(k0 + r) * 32 + lf4], 16);
    }
}

__global__ void __launch_bounds__(128)
gemm_kernel(const float* __restrict__ m,
            const float* __restrict__ Sin_, const float* __restrict__ Sout_,
            float* __restrict__ ain_, float* __restrict__ aout_)
{
    __shared__ float ms[2][128][36];   // 36.9 KB
    __shared__ float ss[2][32][36];    //  9.2 KB

    const int b     = blockIdx.z;
    const int which = blockIdx.y;
    const int nt    = blockIdx.x;

    const float* __restrict__ S  = (which ? Sout_ : Sin_) + (size_t)b * KDIM * 32;
    const float* __restrict__ mb = m + ((size_t)(b * NN + nt * 128)) * 4096
                                     + (size_t)which * 2048;

    const int tid = threadIdx.x;
    const int cg  = tid & 7;
    const int rg  = tid >> 3;
    const int lf4 = cg * 4;

    float acc[8][4];
    #pragma unroll
    for (int i = 0; i < 8; i++)
        { acc[i][0] = 0.f; acc[i][1] = 0.f; acc[i][2] = 0.f; acc[i][3] = 0.f; }

    const int NC = KDIM / 32;   // 64
    stage_chunk(ms[0], ss[0], mb, S, 0, rg, lf4);
    __pipeline_commit();

    for (int c = 0; c < NC; c++) {
        const int buf = c & 1;
        if (c + 1 < NC)
            stage_chunk(ms[buf ^ 1], ss[buf ^ 1], mb, S, (c + 1) * 32, rg, lf4);
        __pipeline_commit();
        __pipeline_wait_prior(1);
        __syncthreads();

        #pragma unroll 4
        for (int k = 0; k < 32; k++) {
            float4 b4 = *(const float4*)&ss[buf][k][lf4];
            #pragma unroll
            for (int i = 0; i < 8; i++) {
                float av = ms[buf][rg + 16 * i][k];
                acc[i][0] += av * b4.x;
                acc[i][1] += av * b4.y;
                acc[i][2] += av * b4.z;
                acc[i][3] += av * b4.w;
            }
        }
        __syncthreads();
    }

    float* __restrict__ outp = which ? aout_ : ain_;
    #pragma unroll
    for (int i = 0; i < 8; i++) {
        int n = nt * 128 + rg + 16 * i;
        float4 v = make_float4(acc[i][0], acc[i][1], acc[i][2], acc[i][3]);
        *(float4*)&outp[((size_t)(b * NN + n)) * 32 + lf4] = v;
    }
}

// ---------------------------------------------------------------------------
// Kernel 3: gates. 256 threads = 8 warps, 8 tokens per warp (weight LDS
// amortized 8x). Grid = 32768/64 = 512 blocks.
// ---------------------------------------------------------------------------
__device__ __forceinline__ float sigmoidf_(float x) {
    return 1.0f / (1.0f + expf(-x));
}

__global__ void __launch_bounds__(256)
gates_kernel(const float* __restrict__ h_in,
             const float* __restrict__ Wz, const float* __restrict__ bz,
             const float* __restrict__ Wr, const float* __restrict__ br,
             const float* __restrict__ Wt, const float* __restrict__ bt,
             const float* __restrict__ ain_, const float* __restrict__ aout_,
             float* __restrict__ hout)
{
    __shared__ float Wzs[96][32];
    __shared__ float Wrs[96][32];
    __shared__ float Wts[96][32];
    __shared__ float cats[8][8][100];   // [warp][token][96 + pad]

    const int tid = threadIdx.x;
    for (int i = tid; i < 32 * 96; i += 256) {
        int j = i / 96, k = i % 96;
        Wzs[k][j] = Wz[i];
        Wrs[k][j] = Wr[i];
        Wts[k][j] = Wt[i];
    }
    __syncthreads();

    const int w    = tid >> 5;
    const int lane = tid & 31;
    const int token0 = blockIdx.x * 64 + w * 8;

    float hj[8], az[8], ar[8], at[8];

    float bzv = __ldg(&bz[lane]);
    float brv = __ldg(&br[lane]);
    float btv = __ldg(&bt[lane]);

    #pragma unroll
    for (int t = 0; t < 8; t++) {
        size_t t32 = (size_t)(token0 + t) * 32;
        float aiv = ain_ [t32 + lane];
        float aov = aout_[t32 + lane];
        hj[t]     = h_in [t32 + lane];
        cats[w][t][lane]      = aiv;
        cats[w][t][32 + lane] = aov;
        cats[w][t][64 + lane] = hj[t];
        az[t] = bzv; ar[t] = brv; at[t] = btv;
    }
    __syncwarp();

    #pragma unroll 4
    for (int k = 0; k < 64; k++) {
        float wz = Wzs[k][lane], wr = Wrs[k][lane], wt = Wts[k][lane];
        #pragma unroll
        for (int t = 0; t < 8; t++) {
            float cv = cats[w][t][k];
            az[t] += cv * wz;
            ar[t] += cv * wr;
            at[t] += cv * wt;
        }
    }
    #pragma unroll 4
    for (int k = 64; k < 96; k++) {
        float wz = Wzs[k][lane], wr = Wrs[k][lane];
        #pragma unroll
        for (int t = 0; t < 8; t++) {
            float cv = cats[w][t][k];
            az[t] += cv * wz;
            ar[t] += cv * wr;
        }
    }

    #pragma unroll
    for (int t = 0; t < 8; t++) {
        float z = sigmoidf_(az[t]);
        float r = sigmoidf_(ar[t]);
        az[t] = z;                       // keep z
        cats[w][t][64 + lane] = r * hj[t];
    }
    __syncwarp();

    #pragma unroll 4
    for (int k = 64; k < 96; k++) {
        float wt = Wts[k][lane];
        #pragma unroll
        for (int t = 0; t < 8; t++)
            at[t] += cats[w][t][k] * wt;
    }

    #pragma unroll
    for (int t = 0; t < 8; t++) {
        float hhat = tanhf(at[t]);
        size_t t32 = (size_t)(token0 + t) * 32;
        hout[t32 + lane] = hj[t] + az[t] * (hhat - hj[t]);
    }
}

// ---------------------------------------------------------------------------
// Kernel 4: final head. One warp per token.
// ---------------------------------------------------------------------------
__global__ void __launch_bounds__(512)
final_kernel(const float* __restrict__ hsrc,
             const float* __restrict__ a,
             const float* __restrict__ W1, const float* __restrict__ b1,
             const float* __restrict__ W2, const float* __restrict__ b2,
             float* __restrict__ out)
{
    __shared__ float W1s[33][32];
    __shared__ float hs[16][32];

    const int tid = threadIdx.x;
    for (int i = tid; i < 32 * 33; i += 512) {
        int j = i / 33, k = i % 33;
        W1s[k][j] = W1[i];
    }

    const int w    = tid >> 5;
    const int lane = tid & 31;
    const int token = blockIdx.x * 16 + w;
    const size_t t32 = (size_t)token * 32;

    hs[w][lane] = hsrc[t32 + lane];
    __syncthreads();

    float acc = __ldg(&b1[lane]);
    #pragma unroll
    for (int k = 0; k < 32; k++)
        acc += hs[w][k] * W1s[k][lane];
    acc += __ldg(&a[token]) * W1s[32][lane];

    float v = tanhf(acc) * __ldg(&W2[lane]);
    #pragma unroll
    for (int off = 16; off > 0; off >>= 1)
        v += __shfl_down_sync(0xFFFFFFFFu, v, off);

    if (lane == 0)
        out[token] = v + __ldg(&b2[0]);
}

// ---------------------------------------------------------------------------
// Launch
// ---------------------------------------------------------------------------
extern "C" void kernel_launch(void* const* d_in, const int* in_sizes, int n_in,
                              void* d_out, int out_size)
{
    const float* x     = (const float*)d_in[0];
    const float* a     = (const float*)d_in[1];
    const float* m     = (const float*)d_in[2];
    const float* W_in  = (const float*)d_in[3];
    const float* b_in  = (const float*)d_in[4];
    const float* W_out = (const float*)d_in[5];
    const float* b_out = (const float*)d_in[6];
    const float* Wz    = (const float*)d_in[7];
    const float* bz    = (const float*)d_in[8];
    const float* Wr    = (const float*)d_in[9];
    const float* br    = (const float*)d_in[10];
    const float* Wt    = (const float*)d_in[11];
    const float* bt    = (const float*)d_in[12];
    const float* W1    = (const float*)d_in[13];
    const float* b1    = (const float*)d_in[14];
    const float* W2    = (const float*)d_in[15];
    const float* b2    = (const float*)d_in[16];
    float* out = (float*)d_out;

    float *pSin, *pSout, *pain, *paout, *ph;
    cudaGetSymbolAddress((void**)&pSin,  g_Sin);
    cudaGetSymbolAddress((void**)&pSout, g_Sout);
    cudaGetSymbolAddress((void**)&pain,  g_ain);
    cudaGetSymbolAddress((void**)&paout, g_aout);
    cudaGetSymbolAddress((void**)&ph,    g_h);

    const int n_tokens = BB * NN;   // 32768

    const float* hsrc = x;
    for (int step = 0; step < NSTEPS; step++) {
        s_kernel<<<n_tokens / 32, 128>>>(hsrc, W_in, b_in, W_out, b_out,
                                         pSin, pSout);

        dim3 ggrid(4, 2, BB);
        gemm_kernel<<<ggrid, 128>>>(m, pSin, pSout, pain, paout);

        gates_kernel<<<n_tokens / 64, 256>>>(hsrc, Wz, bz, Wr, br, Wt, bt,
                                             pain, paout, ph);
        hsrc = ph;
    }

    final_kernel<<<n_tokens / 16, 512>>>(hsrc, a, W1, b1, W2, b2, out);
}

// round 10
// speedup vs baseline: 1.8116x; 1.1193x over previous
#include <cuda_runtime.h>
#include <cuda_fp16.h>
#include <cuda_pipeline.h>
#include <math.h>
#include <stdint.h>

#define BB 64
#define NN 512
#define KDIM 2048
#define NSTEPS 5

#define KCHUNK 32
#define NCHUNK (KDIM / KCHUNK)   // 64

#define LO_SCALE     16384.0f            // 2^14
#define LO_INV_SCALE (1.0f / 16384.0f)   // 2^-14

// A tiles: 128 rows x 32 k fp16, padded row stride 40 halves (80B)
#define A_STRIDE 40
#define B_STRIDE 40
#define AH_OFF 0
#define AL_OFF 10240
#define SH_OFF 20480
#define SL_OFF 23040
#define STAGE_BYTES 25600

// ---------------------------------------------------------------------------
// Scratch
// ---------------------------------------------------------------------------
__device__ __half g_Shi[(size_t)2 * BB * 32 * KDIM];   // 16 MB
__device__ __half g_Slo[(size_t)2 * BB * 32 * KDIM];   // 16 MB (scaled by 2^14)
__device__ float g_ain [(size_t)BB * NN * 32];
__device__ float g_aout[(size_t)BB * NN * 32];
__device__ float g_h   [(size_t)BB * NN * 32];

// ---------------------------------------------------------------------------
// mma.sync fp16 (sm_70+ baseline; compiles for plain sm_103)
// D[16x8] += A[16x16] * B[16x8], fp32 accum
// ---------------------------------------------------------------------------
__device__ __forceinline__ void mma_f16(float* d,
                                        const uint32_t* a,
                                        uint32_t b0, uint32_t b1)
{
    asm volatile(
        "mma.sync.aligned.m16n8k16.row.col.f32.f16.f16.f32 "
        "{%0,%1,%2,%3}, {%4,%5,%6,%7}, {%8,%9}, {%0,%1,%2,%3};"
        : "+f"(d[0]), "+f"(d[1]), "+f"(d[2]), "+f"(d[3])
        : "r"(a[0]), "r"(a[1]), "r"(a[2]), "r"(a[3]), "r"(b0), "r"(b1));
}

// Split x = hi + lo*2^-14, lo stored SCALED to stay in fp16 normal range.
__device__ __forceinline__ void f16_split_scaled(float x, __half& hi, __half& lo) {
    hi = __float2half_rn(x);
    lo = __float2half_rn((x - __half2float(hi)) * LO_SCALE);
}

// ---------------------------------------------------------------------------
// Kernel 1: S projections -> transposed fp16 hi/lo'  S_T[which][b][h'][e*512+n]
// ---------------------------------------------------------------------------
__global__ void __launch_bounds__(256)
s_kernel(const float* __restrict__ h_in,
         const float* __restrict__ W_in,  const float* __restrict__ b_in,
         const float* __restrict__ W_out, const float* __restrict__ b_out,
         __half* __restrict__ Shi, __half* __restrict__ Slo)
{
    __shared__ float Ws[2][128][32];
    __shared__ float hs[32][36];

    const int tid = threadIdx.x;
    for (int i = tid; i < 128 * 32; i += 256) {
        Ws[0][i >> 5][i & 31] = W_in[i];
        Ws[1][i >> 5][i & 31] = W_out[i];
    }
    const int token0 = blockIdx.x * 32;
    {
        int r = tid >> 3, c = (tid & 7) * 4;
        *(float4*)&hs[r][c] = *(const float4*)&h_in[(size_t)(token0 + r) * 32 + c];
    }
    __syncthreads();

    const int w = tid >> 5, lane = tid & 31;
    float hreg[32];
    #pragma unroll
    for (int k = 0; k < 32; k++) hreg[k] = hs[lane][k];

    const int b = token0 >> 9;
    const int n = (token0 & 511) + lane;

    #pragma unroll
    for (int which = 0; which < 2; which++) {
        const float* bias = which ? b_out : b_in;
        #pragma unroll
        for (int jj = 0; jj < 16; jj++) {
            int j = w * 16 + jj;
            float acc = __ldg(&bias[j]);
            #pragma unroll
            for (int k = 0; k < 32; k++)
                acc += hreg[k] * Ws[which][j][k];
            __half hi, lo;
            f16_split_scaled(acc, hi, lo);
            int hp = j >> 2, e = j & 3;
            size_t idx = (((size_t)which * BB + b) * 32 + hp) * KDIM + e * 512 + n;
            Shi[idx] = hi;
            Slo[idx] = lo;
        }
    }
}

// ---------------------------------------------------------------------------
// Kernel 2: scaled-split fp16 GEMM with PROMOTED accumulation.
//   local acch receives mma (RZ-biased adds); flushed into fp32 master via
//   RN FADD every K-chunk -> kills the 128x truncation-bias (2^-18 -> 2^-21).
//   D = master + accm * 2^-14
// Grid (4, 2, 64) = 512 CTAs; 256 threads = 8 warps.
// ---------------------------------------------------------------------------
__global__ void __launch_bounds__(256, 2)
gemm_kernel(const float* __restrict__ m,
            const __half* __restrict__ Shi,
            const __half* __restrict__ Slo,
            float* __restrict__ ain, float* __restrict__ aout)
{
    extern __shared__ char smem[];

    const int b     = blockIdx.z;
    const int which = blockIdx.y;
    const int nt    = blockIdx.x;
    const int tid   = threadIdx.x;
    const int w     = tid >> 5;
    const int lane  = tid & 31;
    const int g     = lane >> 2;
    const int tig   = lane & 3;

    const __half* Sh = Shi + ((size_t)(which * BB + b) * 32) * KDIM;
    const __half* Sl = Slo + ((size_t)(which * BB + b) * 32) * KDIM;
    const float* mb = m + ((size_t)(b * NN + nt * 128)) * 4096
                        + (size_t)which * 2048;

    float acch[4][4];    // local (mma target, flushed per chunk)
    float mast[4][4];    // master (RN accumulation across chunks)
    float accm[4][4];    // mid-term accumulator (bias negligible after 2^-14)
    #pragma unroll
    for (int i = 0; i < 4; i++)
        #pragma unroll
        for (int q = 0; q < 4; q++)
            { acch[i][q] = 0.f; mast[i][q] = 0.f; accm[i][q] = 0.f; }

    const int lrow = tid >> 3;   // 0..31
    const int lseg = tid & 7;    // 0..7

    // prefetch chunk 0 of m into registers
    float4 pf[4];
    #pragma unroll
    for (int p = 0; p < 4; p++)
        pf[p] = *(const float4*)&mb[(size_t)(lrow + 32 * p) * 4096 + lseg * 4];

    for (int c = 0; c < NCHUNK; c++) {
        char* db = smem + (c & 1) * STAGE_BYTES;
        __half* Ah = (__half*)(db + AH_OFF);
        __half* Al = (__half*)(db + AL_OFF);
        __half* Bh = (__half*)(db + SH_OFF);
        __half* Bl = (__half*)(db + SL_OFF);

        // convert prefetched m -> fp16 hi / scaled-lo, STS
        #pragma unroll
        for (int p = 0; p < 4; p++) {
            float xs[4] = {pf[p].x, pf[p].y, pf[p].z, pf[p].w};
            uint32_t hp2[2], lp2[2];
            #pragma unroll
            for (int q = 0; q < 2; q++) {
                __half h0, l0, h1, l1;
                f16_split_scaled(xs[2 * q],     h0, l0);
                f16_split_scaled(xs[2 * q + 1], h1, l1);
                __half2 hh = __halves2half2(h0, h1);
                __half2 ll = __halves2half2(l0, l1);
                hp2[q] = *(uint32_t*)&hh;
                lp2[q] = *(uint32_t*)&ll;
            }
            int row = lrow + 32 * p;
            *(uint2*)&Ah[row * A_STRIDE + lseg * 4] = make_uint2(hp2[0], hp2[1]);
            *(uint2*)&Al[row * A_STRIDE + lseg * 4] = make_uint2(lp2[0], lp2[1]);
        }

        // cp.async the S tiles (32 rows x 32 k fp16 = 64B/row)
        __pipeline_memcpy_async(&Bh[lrow * B_STRIDE + lseg * 4],
                                &Sh[(size_t)lrow * KDIM + c * KCHUNK + lseg * 4], 8);
        __pipeline_memcpy_async(&Bl[lrow * B_STRIDE + lseg * 4],
                                &Sl[(size_t)lrow * KDIM + c * KCHUNK + lseg * 4], 8);
        __pipeline_commit();

        // prefetch next chunk of m
        if (c + 1 < NCHUNK) {
            #pragma unroll
            for (int p = 0; p < 4; p++)
                pf[p] = *(const float4*)&mb[(size_t)(lrow + 32 * p) * 4096
                                            + (c + 1) * KCHUNK + lseg * 4];
        }

        __pipeline_wait_prior(0);
        __syncthreads();

        // compute: 2 k16 steps x 4 n8 tiles x 3 products
        #pragma unroll
        for (int ks = 0; ks < 2; ks++) {
            const int arow = 16 * w + g;
            const int kcol = ks * 16 + tig * 2;
            uint32_t ah[4], al[4];
            ah[0] = *(const uint32_t*)&Ah[(arow)     * A_STRIDE + kcol];
            ah[1] = *(const uint32_t*)&Ah[(arow + 8) * A_STRIDE + kcol];
            ah[2] = *(const uint32_t*)&Ah[(arow)     * A_STRIDE + kcol + 8];
            ah[3] = *(const uint32_t*)&Ah[(arow + 8) * A_STRIDE + kcol + 8];
            al[0] = *(const uint32_t*)&Al[(arow)     * A_STRIDE + kcol];
            al[1] = *(const uint32_t*)&Al[(arow + 8) * A_STRIDE + kcol];
            al[2] = *(const uint32_t*)&Al[(arow)     * A_STRIDE + kcol + 8];
            al[3] = *(const uint32_t*)&Al[(arow + 8) * A_STRIDE + kcol + 8];

            #pragma unroll
            for (int n2 = 0; n2 < 4; n2++) {
                const int brow = n2 * 8 + g;
                uint32_t bh0 = *(const uint32_t*)&Bh[brow * B_STRIDE + kcol];
                uint32_t bh1 = *(const uint32_t*)&Bh[brow * B_STRIDE + kcol + 8];
                uint32_t bl0 = *(const uint32_t*)&Bl[brow * B_STRIDE + kcol];
                uint32_t bl1 = *(const uint32_t*)&Bl[brow * B_STRIDE + kcol + 8];
                mma_f16(acch[n2], ah, bh0, bh1);   // hi @ hi  (into local)
                mma_f16(accm[n2], ah, bl0, bl1);   // hi @ lo' (scaled)
                mma_f16(accm[n2], al, bh0, bh1);   // lo' @ hi (scaled)
            }
        }

        // PROMOTE: flush local into master with RN adds; reset local.
        #pragma unroll
        for (int n2 = 0; n2 < 4; n2++)
            #pragma unroll
            for (int q = 0; q < 4; q++) {
                mast[n2][q] += acch[n2][q];
                acch[n2][q] = 0.f;
            }

        __syncthreads();
    }

    // epilogue: D = master + accm * 2^-14
    float* __restrict__ outp = which ? aout : ain;
    const int row0 = nt * 128 + 16 * w + g;
    #pragma unroll
    for (int n2 = 0; n2 < 4; n2++) {
        int col = n2 * 8 + tig * 2;
        float v0 = mast[n2][0] + accm[n2][0] * LO_INV_SCALE;
        float v1 = mast[n2][1] + accm[n2][1] * LO_INV_SCALE;
        float v2 = mast[n2][2] + accm[n2][2] * LO_INV_SCALE;
        float v3 = mast[n2][3] + accm[n2][3] * LO_INV_SCALE;
        *(float2*)&outp[((size_t)(b * NN + row0))     * 32 + col] = make_float2(v0, v1);
        *(float2*)&outp[((size_t)(b * NN + row0 + 8)) * 32 + col] = make_float2(v2, v3);
    }
}

// ---------------------------------------------------------------------------
// Kernel 3: gates
// ---------------------------------------------------------------------------
__device__ __forceinline__ float sigmoidf_(float x) {
    return 1.0f / (1.0f + expf(-x));
}

__global__ void __launch_bounds__(256)
gates_kernel(const float* __restrict__ h_in,
             const float* __restrict__ Wz, const float* __restrict__ bz,
             const float* __restrict__ Wr, const float* __restrict__ br,
             const float* __restrict__ Wt, const float* __restrict__ bt,
             const float* __restrict__ ain_, const float* __restrict__ aout_,
             float* __restrict__ hout)
{
    __shared__ float Wzs[96][32];
    __shared__ float Wrs[96][32];
    __shared__ float Wts[96][32];
    __shared__ float cats[8][8][100];

    const int tid = threadIdx.x;
    for (int i = tid; i < 32 * 96; i += 256) {
        int j = i / 96, k = i % 96;
        Wzs[k][j] = Wz[i];
        Wrs[k][j] = Wr[i];
        Wts[k][j] = Wt[i];
    }
    __syncthreads();

    const int w = tid >> 5, lane = tid & 31;
    const int token0 = blockIdx.x * 64 + w * 8;

    float hj[8], az[8], ar[8], at[8];
    float bzv = __ldg(&bz[lane]);
    float brv = __ldg(&br[lane]);
    float btv = __ldg(&bt[lane]);

    #pragma unroll
    for (int t = 0; t < 8; t++) {
        size_t t32 = (size_t)(token0 + t) * 32;
        cats[w][t][lane]      = ain_ [t32 + lane];
        cats[w][t][32 + lane] = aout_[t32 + lane];
        hj[t] = h_in[t32 + lane];
        cats[w][t][64 + lane] = hj[t];
        az[t] = bzv; ar[t] = brv; at[t] = btv;
    }
    __syncwarp();

    #pragma unroll 4
    for (int k = 0; k < 64; k++) {
        float wz = Wzs[k][lane], wr = Wrs[k][lane], wt = Wts[k][lane];
        #pragma unroll
        for (int t = 0; t < 8; t++) {
            float cv = cats[w][t][k];
            az[t] += cv * wz;
            ar[t] += cv * wr;
            at[t] += cv * wt;
        }
    }
    #pragma unroll 4
    for (int k = 64; k < 96; k++) {
        float wz = Wzs[k][lane], wr = Wrs[k][lane];
        #pragma unroll
        for (int t = 0; t < 8; t++) {
            float cv = cats[w][t][k];
            az[t] += cv * wz;
            ar[t] += cv * wr;
        }
    }

    #pragma unroll
    for (int t = 0; t < 8; t++) {
        float z = sigmoidf_(az[t]);
        float r = sigmoidf_(ar[t]);
        az[t] = z;
        cats[w][t][64 + lane] = r * hj[t];
    }
    __syncwarp();

    #pragma unroll 4
    for (int k = 64; k < 96; k++) {
        float wt = Wts[k][lane];
        #pragma unroll
        for (int t = 0; t < 8; t++)
            at[t] += cats[w][t][k] * wt;
    }

    #pragma unroll
    for (int t = 0; t < 8; t++) {
        float hhat = tanhf(at[t]);
        size_t t32 = (size_t)(token0 + t) * 32;
        hout[t32 + lane] = hj[t] + az[t] * (hhat - hj[t]);
    }
}

// ---------------------------------------------------------------------------
// Kernel 4: final head
// ---------------------------------------------------------------------------
__global__ void __launch_bounds__(512)
final_kernel(const float* __restrict__ hsrc,
             const float* __restrict__ a,
             const float* __restrict__ W1, const float* __restrict__ b1,
             const float* __restrict__ W2, const float* __restrict__ b2,
             float* __restrict__ out)
{
    __shared__ float W1s[33][32];
    __shared__ float hs[16][32];

    const int tid = threadIdx.x;
    for (int i = tid; i < 32 * 33; i += 512) {
        int j = i / 33, k = i % 33;
        W1s[k][j] = W1[i];
    }

    const int w = tid >> 5, lane = tid & 31;
    const int token = blockIdx.x * 16 + w;
    const size_t t32 = (size_t)token * 32;

    hs[w][lane] = hsrc[t32 + lane];
    __syncthreads();

    float acc = __ldg(&b1[lane]);
    #pragma unroll
    for (int k = 0; k < 32; k++)
        acc += hs[w][k] * W1s[k][lane];
    acc += __ldg(&a[token]) * W1s[32][lane];

    float v = tanhf(acc) * __ldg(&W2[lane]);
    #pragma unroll
    for (int off = 16; off > 0; off >>= 1)
        v += __shfl_down_sync(0xFFFFFFFFu, v, off);

    if (lane == 0)
        out[token] = v + __ldg(&b2[0]);
}

// ---------------------------------------------------------------------------
// Launch
// ---------------------------------------------------------------------------
extern "C" void kernel_launch(void* const* d_in, const int* in_sizes, int n_in,
                              void* d_out, int out_size)
{
    const float* x     = (const float*)d_in[0];
    const float* a     = (const float*)d_in[1];
    const float* m     = (const float*)d_in[2];
    const float* W_in  = (const float*)d_in[3];
    const float* b_in  = (const float*)d_in[4];
    const float* W_out = (const float*)d_in[5];
    const float* b_out = (const float*)d_in[6];
    const float* Wz    = (const float*)d_in[7];
    const float* bz    = (const float*)d_in[8];
    const float* Wr    = (const float*)d_in[9];
    const float* br    = (const float*)d_in[10];
    const float* Wt    = (const float*)d_in[11];
    const float* bt    = (const float*)d_in[12];
    const float* W1    = (const float*)d_in[13];
    const float* b1    = (const float*)d_in[14];
    const float* W2    = (const float*)d_in[15];
    const float* b2    = (const float*)d_in[16];
    float* out = (float*)d_out;

    __half *pShi, *pSlo;
    float *pain, *paout, *ph;
    cudaGetSymbolAddress((void**)&pShi,  g_Shi);
    cudaGetSymbolAddress((void**)&pSlo,  g_Slo);
    cudaGetSymbolAddress((void**)&pain,  g_ain);
    cudaGetSymbolAddress((void**)&paout, g_aout);
    cudaGetSymbolAddress((void**)&ph,    g_h);

    const int dyn_smem = 2 * STAGE_BYTES;   // 51200
    cudaFuncSetAttribute(gemm_kernel,
                         cudaFuncAttributeMaxDynamicSharedMemorySize, dyn_smem);

    const int n_tokens = BB * NN;   // 32768

    const float* hsrc = x;
    for (int step = 0; step < NSTEPS; step++) {
        s_kernel<<<n_tokens / 32, 256>>>(hsrc, W_in, b_in, W_out, b_out,
                                         pShi, pSlo);

        dim3 ggrid(4, 2, BB);
        gemm_kernel<<<ggrid, 256, dyn_smem>>>(m, pShi, pSlo, pain, paout);

        gates_kernel<<<n_tokens / 64, 256>>>(hsrc, Wz, bz, Wr, br, Wt, bt,
                                             pain, paout, ph);
        hsrc = ph;
    }

    final_kernel<<<n_tokens / 16, 512>>>(hsrc, a, W1, b1, W2, b2, out);
}

// round 11
// speedup vs baseline: 1.9314x; 1.0661x over previous
#include <cuda_runtime.h>
#include <cuda_fp16.h>
#include <cuda_pipeline.h>
#include <math.h>
#include <stdint.h>

#define BB 64
#define NN 512
#define KDIM 2048
#define NSTEPS 5

#define KCHUNK 64
#define NCHUNK (KDIM / KCHUNK)   // 32

#define LO_SCALE     16384.0f            // 2^14
#define LO_INV_SCALE (1.0f / 16384.0f)   // 2^-14

// smem tiles (halves), padded row stride 72 halves (144B = 36 words)
#define T_STRIDE 72
#define AH_OFF 0
#define AL_OFF 18432
#define BH_OFF 36864
#define BL_OFF 41472
#define STAGE_BYTES 46080   // x2 buffers = 92160

// ---------------------------------------------------------------------------
// Scratch
// ---------------------------------------------------------------------------
__device__ __half g_mhi[(size_t)BB * NN * 2 * KDIM];   // 268 MB
__device__ __half g_mlo[(size_t)BB * NN * 2 * KDIM];   // 268 MB (scaled 2^14)
__device__ __half g_Shi[(size_t)2 * BB * 32 * KDIM];   // 16 MB
__device__ __half g_Slo[(size_t)2 * BB * 32 * KDIM];   // 16 MB (scaled 2^14)
__device__ float g_ain [(size_t)BB * NN * 32];
__device__ float g_aout[(size_t)BB * NN * 32];
__device__ float g_h   [(size_t)BB * NN * 32];

// ---------------------------------------------------------------------------
// mma.sync fp16 (sm_70+ baseline; compiles for plain sm_103)
// ---------------------------------------------------------------------------
__device__ __forceinline__ void mma_f16(float* d,
                                        const uint32_t* a,
                                        uint32_t b0, uint32_t b1)
{
    asm volatile(
        "mma.sync.aligned.m16n8k16.row.col.f32.f16.f16.f32 "
        "{%0,%1,%2,%3}, {%4,%5,%6,%7}, {%8,%9}, {%0,%1,%2,%3};"
        : "+f"(d[0]), "+f"(d[1]), "+f"(d[2]), "+f"(d[3])
        : "r"(a[0]), "r"(a[1]), "r"(a[2]), "r"(a[3]), "r"(b0), "r"(b1));
}

// Split x = hi + lo*2^-14, lo stored SCALED to stay in fp16 normal range.
__device__ __forceinline__ void f16_split_scaled(float x, __half& hi, __half& lo) {
    hi = __float2half_rn(x);
    lo = __float2half_rn((x - __half2float(hi)) * LO_SCALE);
}

// ---------------------------------------------------------------------------
// Kernel 0: one-time split of m into fp16 hi / scaled-lo (same layout as m).
// 134,217,728 elements; 8 per thread; grid 65536 x 256.
// ---------------------------------------------------------------------------
__global__ void __launch_bounds__(256)
msplit_kernel(const float* __restrict__ m,
              __half* __restrict__ mhi, __half* __restrict__ mlo)
{
    size_t idx = ((size_t)blockIdx.x * 256 + threadIdx.x) * 8;
    float4 v0 = *(const float4*)&m[idx];
    float4 v1 = *(const float4*)&m[idx + 4];
    float xs[8] = {v0.x, v0.y, v0.z, v0.w, v1.x, v1.y, v1.z, v1.w};
    __half h[8], l[8];
    #pragma unroll
    for (int i = 0; i < 8; i++) f16_split_scaled(xs[i], h[i], l[i]);
    uint32_t hp[4], lp[4];
    #pragma unroll
    for (int q = 0; q < 4; q++) {
        __half2 hh = __halves2half2(h[2*q], h[2*q+1]);
        __half2 ll = __halves2half2(l[2*q], l[2*q+1]);
        hp[q] = *(uint32_t*)&hh;
        lp[q] = *(uint32_t*)&ll;
    }
    *(uint4*)&mhi[idx] = make_uint4(hp[0], hp[1], hp[2], hp[3]);
    *(uint4*)&mlo[idx] = make_uint4(lp[0], lp[1], lp[2], lp[3]);
}

// ---------------------------------------------------------------------------
// Kernel 1: S projections -> transposed fp16 hi/lo'  S_T[which][b][h'][e*512+n]
// (float4-vectorized W loads: 4 FMA per LDS.128)
// ---------------------------------------------------------------------------
__global__ void __launch_bounds__(256)
s_kernel(const float* __restrict__ h_in,
         const float* __restrict__ W_in,  const float* __restrict__ b_in,
         const float* __restrict__ W_out, const float* __restrict__ b_out,
         __half* __restrict__ Shi, __half* __restrict__ Slo)
{
    __shared__ float Ws[2][128][32];
    __shared__ float hs[32][36];

    const int tid = threadIdx.x;
    for (int i = tid; i < 128 * 32; i += 256) {
        Ws[0][i >> 5][i & 31] = W_in[i];
        Ws[1][i >> 5][i & 31] = W_out[i];
    }
    const int token0 = blockIdx.x * 32;
    {
        int r = tid >> 3, c = (tid & 7) * 4;
        *(float4*)&hs[r][c] = *(const float4*)&h_in[(size_t)(token0 + r) * 32 + c];
    }
    __syncthreads();

    const int w = tid >> 5, lane = tid & 31;
    float hreg[32];
    #pragma unroll
    for (int k = 0; k < 32; k++) hreg[k] = hs[lane][k];

    const int b = token0 >> 9;
    const int n = (token0 & 511) + lane;

    #pragma unroll
    for (int which = 0; which < 2; which++) {
        const float* bias = which ? b_out : b_in;
        #pragma unroll
        for (int jj = 0; jj < 16; jj++) {
            int j = w * 16 + jj;
            float acc = __ldg(&bias[j]);
            #pragma unroll
            for (int k4 = 0; k4 < 8; k4++) {
                float4 wv = *(const float4*)&Ws[which][j][k4 * 4];
                acc += hreg[k4*4+0] * wv.x;
                acc += hreg[k4*4+1] * wv.y;
                acc += hreg[k4*4+2] * wv.z;
                acc += hreg[k4*4+3] * wv.w;
            }
            __half hi, lo;
            f16_split_scaled(acc, hi, lo);
            int hp = j >> 2, e = j & 3;
            size_t idx = (((size_t)which * BB + b) * 32 + hp) * KDIM + e * 512 + n;
            Shi[idx] = hi;
            Slo[idx] = lo;
        }
    }
}

// ---------------------------------------------------------------------------
// Kernel 2: scaled-split fp16 GEMM, all operands pre-split in global.
// Staging = pure cp.async (no LDG/convert/STS). K chunks of 64, double buffer.
//   master = sum(mh@Sh) promoted per chunk; D = master + accm * 2^-14
// Grid (4, 2, 64) = 512 CTAs; 256 threads = 8 warps.
// ---------------------------------------------------------------------------
__global__ void __launch_bounds__(256, 2)
gemm_kernel(const __half* __restrict__ mhi, const __half* __restrict__ mlo,
            const __half* __restrict__ Shi, const __half* __restrict__ Slo,
            float* __restrict__ ain, float* __restrict__ aout)
{
    extern __shared__ char smem[];

    const int b     = blockIdx.z;
    const int which = blockIdx.y;
    const int nt    = blockIdx.x;
    const int tid   = threadIdx.x;
    const int w     = tid >> 5;
    const int lane  = tid & 31;
    const int g     = lane >> 2;
    const int tig   = lane & 3;

    const __half* Sh = Shi + ((size_t)(which * BB + b) * 32) * KDIM;
    const __half* Sl = Slo + ((size_t)(which * BB + b) * 32) * KDIM;
    const size_t mbase = ((size_t)(b * NN + nt * 128)) * 4096 + (size_t)which * 2048;
    const __half* mh = mhi + mbase;
    const __half* ml = mlo + mbase;

    float acch[4][4], mast[4][4], accm[4][4];
    #pragma unroll
    for (int i = 0; i < 4; i++)
        #pragma unroll
        for (int q = 0; q < 4; q++)
            { acch[i][q] = 0.f; mast[i][q] = 0.f; accm[i][q] = 0.f; }

    // cp.async staging helper indices
    const int br = tid >> 3;     // 0..31 (B rows / A row group base)
    const int bs = tid & 7;      // 0..7  (16B segment)

    // stage(chunk c) into buffer buf
    auto stage = [&](int c, int buf) {
        char* db = smem + buf * STAGE_BYTES;
        __half* Ah = (__half*)(db + AH_OFF);
        __half* Al = (__half*)(db + AL_OFF);
        __half* Bh = (__half*)(db + BH_OFF);
        __half* Bl = (__half*)(db + BL_OFF);
        const int k0 = c * KCHUNK;
        #pragma unroll
        for (int i = 0; i < 4; i++) {
            int slot = tid + 256 * i;          // 0..1023
            int r = slot >> 3, s = slot & 7;   // r 0..127
            size_t gsrc = (size_t)r * 4096 + k0 + s * 8;
            uint32_t d = (uint32_t)(r * T_STRIDE + s * 8);
            __pipeline_memcpy_async(&Ah[d], &mh[gsrc], 16);
            __pipeline_memcpy_async(&Al[d], &ml[gsrc], 16);
        }
        {
            size_t gsrc = (size_t)br * KDIM + k0 + bs * 8;
            uint32_t d = (uint32_t)(br * T_STRIDE + bs * 8);
            __pipeline_memcpy_async(&Bh[d], &Sh[gsrc], 16);
            __pipeline_memcpy_async(&Bl[d], &Sl[gsrc], 16);
        }
        __pipeline_commit();
    };

    stage(0, 0);

    for (int c = 0; c < NCHUNK; c++) {
        const int buf = c & 1;
        if (c + 1 < NCHUNK) {
            stage(c + 1, buf ^ 1);
            __pipeline_wait_prior(1);
        } else {
            __pipeline_wait_prior(0);
        }
        __syncthreads();

        char* db = smem + buf * STAGE_BYTES;
        __half* Ah = (__half*)(db + AH_OFF);
        __half* Al = (__half*)(db + AL_OFF);
        __half* Bh = (__half*)(db + BH_OFF);
        __half* Bl = (__half*)(db + BL_OFF);

        // 4 k16 steps x 4 n8 tiles x 3 products
        #pragma unroll
        for (int ks = 0; ks < 4; ks++) {
            const int arow = 16 * w + g;
            const int kcol = ks * 16 + tig * 2;
            uint32_t ah[4], al[4];
            ah[0] = *(const uint32_t*)&Ah[(arow)     * T_STRIDE + kcol];
            ah[1] = *(const uint32_t*)&Ah[(arow + 8) * T_STRIDE + kcol];
            ah[2] = *(const uint32_t*)&Ah[(arow)     * T_STRIDE + kcol + 8];
            ah[3] = *(const uint32_t*)&Ah[(arow + 8) * T_STRIDE + kcol + 8];
            al[0] = *(const uint32_t*)&Al[(arow)     * T_STRIDE + kcol];
            al[1] = *(const uint32_t*)&Al[(arow + 8) * T_STRIDE + kcol];
            al[2] = *(const uint32_t*)&Al[(arow)     * T_STRIDE + kcol + 8];
            al[3] = *(const uint32_t*)&Al[(arow + 8) * T_STRIDE + kcol + 8];

            #pragma unroll
            for (int n2 = 0; n2 < 4; n2++) {
                const int brow = n2 * 8 + g;
                uint32_t bh0 = *(const uint32_t*)&Bh[brow * T_STRIDE + kcol];
                uint32_t bh1 = *(const uint32_t*)&Bh[brow * T_STRIDE + kcol + 8];
                uint32_t bl0 = *(const uint32_t*)&Bl[brow * T_STRIDE + kcol];
                uint32_t bl1 = *(const uint32_t*)&Bl[brow * T_STRIDE + kcol + 8];
                mma_f16(acch[n2], ah, bh0, bh1);   // hi @ hi  (local)
                mma_f16(accm[n2], ah, bl0, bl1);   // hi @ lo' (scaled)
                mma_f16(accm[n2], al, bh0, bh1);   // lo' @ hi (scaled)
            }
        }

        // PROMOTE: flush local into master with RN adds; reset local.
        #pragma unroll
        for (int n2 = 0; n2 < 4; n2++)
            #pragma unroll
            for (int q = 0; q < 4; q++) {
                mast[n2][q] += acch[n2][q];
                acch[n2][q] = 0.f;
            }

        __syncthreads();   // reads done before next stage overwrites this buf
    }

    // epilogue: D = master + accm * 2^-14
    float* __restrict__ outp = which ? aout : ain;
    const int row0 = nt * 128 + 16 * w + g;
    #pragma unroll
    for (int n2 = 0; n2 < 4; n2++) {
        int col = n2 * 8 + tig * 2;
        float v0 = mast[n2][0] + accm[n2][0] * LO_INV_SCALE;
        float v1 = mast[n2][1] + accm[n2][1] * LO_INV_SCALE;
        float v2 = mast[n2][2] + accm[n2][2] * LO_INV_SCALE;
        float v3 = mast[n2][3] + accm[n2][3] * LO_INV_SCALE;
        *(float2*)&outp[((size_t)(b * NN + row0))     * 32 + col] = make_float2(v0, v1);
        *(float2*)&outp[((size_t)(b * NN + row0 + 8)) * 32 + col] = make_float2(v2, v3);
    }
}

// ---------------------------------------------------------------------------
// Kernel 3: gates
// ---------------------------------------------------------------------------
__device__ __forceinline__ float sigmoidf_(float x) {
    return 1.0f / (1.0f + expf(-x));
}

__global__ void __launch_bounds__(256)
gates_kernel(const float* __restrict__ h_in,
             const float* __restrict__ Wz, const float* __restrict__ bz,
             const float* __restrict__ Wr, const float* __restrict__ br,
             const float* __restrict__ Wt, const float* __restrict__ bt,
             const float* __restrict__ ain_, const float* __restrict__ aout_,
             float* __restrict__ hout)
{
    __shared__ float Wzs[96][32];
    __shared__ float Wrs[96][32];
    __shared__ float Wts[96][32];
    __shared__ float cats[8][8][100];

    const int tid = threadIdx.x;
    for (int i = tid; i < 32 * 96; i += 256) {
        int j = i / 96, k = i % 96;
        Wzs[k][j] = Wz[i];
        Wrs[k][j] = Wr[i];
        Wts[k][j] = Wt[i];
    }
    __syncthreads();

    const int w = tid >> 5, lane = tid & 31;
    const int token0 = blockIdx.x * 64 + w * 8;

    float hj[8], az[8], ar[8], at[8];
    float bzv = __ldg(&bz[lane]);
    float brv = __ldg(&br[lane]);
    float btv = __ldg(&bt[lane]);

    #pragma unroll
    for (int t = 0; t < 8; t++) {
        size_t t32 = (size_t)(token0 + t) * 32;
        cats[w][t][lane]      = ain_ [t32 + lane];
        cats[w][t][32 + lane] = aout_[t32 + lane];
        hj[t] = h_in[t32 + lane];
        cats[w][t][64 + lane] = hj[t];
        az[t] = bzv; ar[t] = brv; at[t] = btv;
    }
    __syncwarp();

    #pragma unroll 4
    for (int k = 0; k < 64; k++) {
        float wz = Wzs[k][lane], wr = Wrs[k][lane], wt = Wts[k][lane];
        #pragma unroll
        for (int t = 0; t < 8; t++) {
            float cv = cats[w][t][k];
            az[t] += cv * wz;
            ar[t] += cv * wr;
            at[t] += cv * wt;
        }
    }
    #pragma unroll 4
    for (int k = 64; k < 96; k++) {
        float wz = Wzs[k][lane], wr = Wrs[k][lane];
        #pragma unroll
        for (int t = 0; t < 8; t++) {
            float cv = cats[w][t][k];
            az[t] += cv * wz;
            ar[t] += cv * wr;
        }
    }

    #pragma unroll
    for (int t = 0; t < 8; t++) {
        float z = sigmoidf_(az[t]);
        float r = sigmoidf_(ar[t]);
        az[t] = z;
        cats[w][t][64 + lane] = r * hj[t];
    }
    __syncwarp();

    #pragma unroll 4
    for (int k = 64; k < 96; k++) {
        float wt = Wts[k][lane];
        #pragma unroll
        for (int t = 0; t < 8; t++)
            at[t] += cats[w][t][k] * wt;
    }

    #pragma unroll
    for (int t = 0; t < 8; t++) {
        float hhat = tanhf(at[t]);
        size_t t32 = (size_t)(token0 + t) * 32;
        hout[t32 + lane] = hj[t] + az[t] * (hhat - hj[t]);
    }
}

// ---------------------------------------------------------------------------
// Kernel 4: final head
// ---------------------------------------------------------------------------
__global__ void __launch_bounds__(512)
final_kernel(const float* __restrict__ hsrc,
             const float* __restrict__ a,
             const float* __restrict__ W1, const float* __restrict__ b1,
             const float* __restrict__ W2, const float* __restrict__ b2,
             float* __restrict__ out)
{
    __shared__ float W1s[33][32];
    __shared__ float hs[16][32];

    const int tid = threadIdx.x;
    for (int i = tid; i < 32 * 33; i += 512) {
        int j = i / 33, k = i % 33;
        W1s[k][j] = W1[i];
    }

    const int w = tid >> 5, lane = tid & 31;
    const int token = blockIdx.x * 16 + w;
    const size_t t32 = (size_t)token * 32;

    hs[w][lane] = hsrc[t32 + lane];
    __syncthreads();

    float acc = __ldg(&b1[lane]);
    #pragma unroll
    for (int k = 0; k < 32; k++)
        acc += hs[w][k] * W1s[k][lane];
    acc += __ldg(&a[token]) * W1s[32][lane];

    float v = tanhf(acc) * __ldg(&W2[lane]);
    #pragma unroll
    for (int off = 16; off > 0; off >>= 1)
        v += __shfl_down_sync(0xFFFFFFFFu, v, off);

    if (lane == 0)
        out[token] = v + __ldg(&b2[0]);
}

// ---------------------------------------------------------------------------
// Launch
// ---------------------------------------------------------------------------
extern "C" void kernel_launch(void* const* d_in, const int* in_sizes, int n_in,
                              void* d_out, int out_size)
{
    const float* x     = (const float*)d_in[0];
    const float* a     = (const float*)d_in[1];
    const float* m     = (const float*)d_in[2];
    const float* W_in  = (const float*)d_in[3];
    const float* b_in  = (const float*)d_in[4];
    const float* W_out = (const float*)d_in[5];
    const float* b_out = (const float*)d_in[6];
    const float* Wz    = (const float*)d_in[7];
    const float* bz    = (const float*)d_in[8];
    const float* Wr    = (const float*)d_in[9];
    const float* br    = (const float*)d_in[10];
    const float* Wt    = (const float*)d_in[11];
    const float* bt    = (const float*)d_in[12];
    const float* W1    = (const float*)d_in[13];
    const float* b1    = (const float*)d_in[14];
    const float* W2    = (const float*)d_in[15];
    const float* b2    = (const float*)d_in[16];
    float* out = (float*)d_out;

    __half *pmhi, *pmlo, *pShi, *pSlo;
    float *pain, *paout, *ph;
    cudaGetSymbolAddress((void**)&pmhi,  g_mhi);
    cudaGetSymbolAddress((void**)&pmlo,  g_mlo);
    cudaGetSymbolAddress((void**)&pShi,  g_Shi);
    cudaGetSymbolAddress((void**)&pSlo,  g_Slo);
    cudaGetSymbolAddress((void**)&pain,  g_ain);
    cudaGetSymbolAddress((void**)&paout, g_aout);
    cudaGetSymbolAddress((void**)&ph,    g_h);

    const int dyn_smem = 2 * STAGE_BYTES;   // 92160
    cudaFuncSetAttribute(gemm_kernel,
                         cudaFuncAttributeMaxDynamicSharedMemorySize, dyn_smem);

    const int n_tokens = BB * NN;   // 32768

    // one-time m split (per call; m is constant across the step loop)
    msplit_kernel<<<65536, 256>>>(m, pmhi, pmlo);

    const float* hsrc = x;
    for (int step = 0; step < NSTEPS; step++) {
        s_kernel<<<n_tokens / 32, 256>>>(hsrc, W_in, b_in, W_out, b_out,
                                         pShi, pSlo);

        dim3 ggrid(4, 2, BB);
        gemm_kernel<<<ggrid, 256, dyn_smem>>>(pmhi, pmlo, pShi, pSlo,
                                              pain, paout);

        gates_kernel<<<n_tokens / 64, 256>>>(hsrc, Wz, bz, Wr, br, Wt, bt,
                                             pain, paout, ph);
        hsrc = ph;
    }

    final_kernel<<<n_tokens / 16, 512>>>(hsrc, a, W1, b1, W2, b2, out);
}

// round 12
// speedup vs baseline: 2.1484x; 1.1123x over previous
#include <cuda_runtime.h>
#include <cuda_fp16.h>
#include <cuda_pipeline.h>
#include <math.h>
#include <stdint.h>

#define BB 64
#define NN 512
#define KDIM 2048
#define NSTEPS 5

#define KCHUNK 64
#define NCHUNK (KDIM / KCHUNK)   // 32

#define LO_SCALE     16384.0f            // 2^14
#define LO_INV_SCALE (1.0f / 16384.0f)   // 2^-14

// smem tiles (halves), padded row stride 72 halves (144B = 36 words)
#define T_STRIDE 72
#define AH_OFF 0
#define AL_OFF 18432
#define BH_OFF 36864
#define BL_OFF 41472
#define STAGE_BYTES 46080   // x2 buffers = 92160

// ---------------------------------------------------------------------------
// Scratch
// ---------------------------------------------------------------------------
__device__ __half g_mhi[(size_t)BB * NN * 2 * KDIM];   // 268 MB
__device__ __half g_mlo[(size_t)BB * NN * 2 * KDIM];   // 268 MB (scaled 2^14)
__device__ __half g_Shi[(size_t)2 * BB * 32 * KDIM];   // 16 MB
__device__ __half g_Slo[(size_t)2 * BB * 32 * KDIM];   // 16 MB (scaled 2^14)
__device__ float g_ain [(size_t)BB * NN * 32];
__device__ float g_aout[(size_t)BB * NN * 32];
__device__ float g_h   [(size_t)BB * NN * 32];

// ---------------------------------------------------------------------------
// mma.sync fp16 (sm_70+ baseline; compiles for plain sm_103)
// ---------------------------------------------------------------------------
__device__ __forceinline__ void mma_f16(float* d,
                                        const uint32_t* a,
                                        uint32_t b0, uint32_t b1)
{
    asm volatile(
        "mma.sync.aligned.m16n8k16.row.col.f32.f16.f16.f32 "
        "{%0,%1,%2,%3}, {%4,%5,%6,%7}, {%8,%9}, {%0,%1,%2,%3};"
        : "+f"(d[0]), "+f"(d[1]), "+f"(d[2]), "+f"(d[3])
        : "r"(a[0]), "r"(a[1]), "r"(a[2]), "r"(a[3]), "r"(b0), "r"(b1));
}

// Split x = hi + lo*2^-14, lo stored SCALED to stay in fp16 normal range.
__device__ __forceinline__ void f16_split_scaled(float x, __half& hi, __half& lo) {
    hi = __float2half_rn(x);
    lo = __float2half_rn((x - __half2float(hi)) * LO_SCALE);
}

// split 8 floats into packed hi/lo uint4
__device__ __forceinline__ void split8(const float* xs, uint4& hq, uint4& lq) {
    __half h[8], l[8];
    #pragma unroll
    for (int i = 0; i < 8; i++) f16_split_scaled(xs[i], h[i], l[i]);
    uint32_t hp[4], lp[4];
    #pragma unroll
    for (int q = 0; q < 4; q++) {
        __half2 hh = __halves2half2(h[2*q], h[2*q+1]);
        __half2 ll = __halves2half2(l[2*q], l[2*q+1]);
        hp[q] = *(uint32_t*)&hh;
        lp[q] = *(uint32_t*)&ll;
    }
    hq = make_uint4(hp[0], hp[1], hp[2], hp[3]);
    lq = make_uint4(lp[0], lp[1], lp[2], lp[3]);
}

// ---------------------------------------------------------------------------
// Kernel 1: S projections -> transposed fp16 hi/lo'  S_T[which][b][h'][e*512+n]
// ---------------------------------------------------------------------------
__global__ void __launch_bounds__(256)
s_kernel(const float* __restrict__ h_in,
         const float* __restrict__ W_in,  const float* __restrict__ b_in,
         const float* __restrict__ W_out, const float* __restrict__ b_out,
         __half* __restrict__ Shi, __half* __restrict__ Slo)
{
    __shared__ float Ws[2][128][32];
    __shared__ float hs[32][36];

    const int tid = threadIdx.x;
    for (int i = tid; i < 128 * 32; i += 256) {
        Ws[0][i >> 5][i & 31] = W_in[i];
        Ws[1][i >> 5][i & 31] = W_out[i];
    }
    const int token0 = blockIdx.x * 32;
    {
        int r = tid >> 3, c = (tid & 7) * 4;
        *(float4*)&hs[r][c] = *(const float4*)&h_in[(size_t)(token0 + r) * 32 + c];
    }
    __syncthreads();

    const int w = tid >> 5, lane = tid & 31;
    float hreg[32];
    #pragma unroll
    for (int k = 0; k < 32; k++) hreg[k] = hs[lane][k];

    const int b = token0 >> 9;
    const int n = (token0 & 511) + lane;

    #pragma unroll
    for (int which = 0; which < 2; which++) {
        const float* bias = which ? b_out : b_in;
        #pragma unroll
        for (int jj = 0; jj < 16; jj++) {
            int j = w * 16 + jj;
            float acc = __ldg(&bias[j]);
            #pragma unroll
            for (int k4 = 0; k4 < 8; k4++) {
                float4 wv = *(const float4*)&Ws[which][j][k4 * 4];
                acc += hreg[k4*4+0] * wv.x;
                acc += hreg[k4*4+1] * wv.y;
                acc += hreg[k4*4+2] * wv.z;
                acc += hreg[k4*4+3] * wv.w;
            }
            __half hi, lo;
            f16_split_scaled(acc, hi, lo);
            int hp = j >> 2, e = j & 3;
            size_t idx = (((size_t)which * BB + b) * 32 + hp) * KDIM + e * 512 + n;
            Shi[idx] = hi;
            Slo[idx] = lo;
        }
    }
}

// ---------------------------------------------------------------------------
// Shared GEMM compute body (identical math for both gemm variants)
// ---------------------------------------------------------------------------
struct GemmCtx {
    float acch[4][4], mast[4][4], accm[4][4];
};

__device__ __forceinline__ void gemm_compute_chunk(
    GemmCtx& cx, char* db, int w, int g, int tig)
{
    __half* Ah = (__half*)(db + AH_OFF);
    __half* Al = (__half*)(db + AL_OFF);
    __half* Bh = (__half*)(db + BH_OFF);
    __half* Bl = (__half*)(db + BL_OFF);

    #pragma unroll
    for (int ks = 0; ks < 4; ks++) {
        const int arow = 16 * w + g;
        const int kcol = ks * 16 + tig * 2;
        uint32_t ah[4], al[4];
        ah[0] = *(const uint32_t*)&Ah[(arow)     * T_STRIDE + kcol];
        ah[1] = *(const uint32_t*)&Ah[(arow + 8) * T_STRIDE + kcol];
        ah[2] = *(const uint32_t*)&Ah[(arow)     * T_STRIDE + kcol + 8];
        ah[3] = *(const uint32_t*)&Ah[(arow + 8) * T_STRIDE + kcol + 8];
        al[0] = *(const uint32_t*)&Al[(arow)     * T_STRIDE + kcol];
        al[1] = *(const uint32_t*)&Al[(arow + 8) * T_STRIDE + kcol];
        al[2] = *(const uint32_t*)&Al[(arow)     * T_STRIDE + kcol + 8];
        al[3] = *(const uint32_t*)&Al[(arow + 8) * T_STRIDE + kcol + 8];

        #pragma unroll
        for (int n2 = 0; n2 < 4; n2++) {
            const int brow = n2 * 8 + g;
            uint32_t bh0 = *(const uint32_t*)&Bh[brow * T_STRIDE + kcol];
            uint32_t bh1 = *(const uint32_t*)&Bh[brow * T_STRIDE + kcol + 8];
            uint32_t bl0 = *(const uint32_t*)&Bl[brow * T_STRIDE + kcol];
            uint32_t bl1 = *(const uint32_t*)&Bl[brow * T_STRIDE + kcol + 8];
            mma_f16(cx.acch[n2], ah, bh0, bh1);
            mma_f16(cx.accm[n2], ah, bl0, bl1);
            mma_f16(cx.accm[n2], al, bh0, bh1);
        }
    }
    // PROMOTE
    #pragma unroll
    for (int n2 = 0; n2 < 4; n2++)
        #pragma unroll
        for (int q = 0; q < 4; q++) {
            cx.mast[n2][q] += cx.acch[n2][q];
            cx.acch[n2][q] = 0.f;
        }
}

__device__ __forceinline__ void gemm_epilogue(
    GemmCtx& cx, float* outp, int b, int nt, int w, int g, int tig)
{
    const int row0 = nt * 128 + 16 * w + g;
    #pragma unroll
    for (int n2 = 0; n2 < 4; n2++) {
        int col = n2 * 8 + tig * 2;
        float v0 = cx.mast[n2][0] + cx.accm[n2][0] * LO_INV_SCALE;
        float v1 = cx.mast[n2][1] + cx.accm[n2][1] * LO_INV_SCALE;
        float v2 = cx.mast[n2][2] + cx.accm[n2][2] * LO_INV_SCALE;
        float v3 = cx.mast[n2][3] + cx.accm[n2][3] * LO_INV_SCALE;
        *(float2*)&outp[((size_t)(b * NN + row0))     * 32 + col] = make_float2(v0, v1);
        *(float2*)&outp[((size_t)(b * NN + row0 + 8)) * 32 + col] = make_float2(v2, v3);
    }
}

// ---------------------------------------------------------------------------
// Kernel 2a: steady-state GEMM (steps 1..4), pure cp.async staging.
// ---------------------------------------------------------------------------
__global__ void __launch_bounds__(256, 2)
gemm_kernel(const __half* __restrict__ mhi, const __half* __restrict__ mlo,
            const __half* __restrict__ Shi, const __half* __restrict__ Slo,
            float* __restrict__ ain, float* __restrict__ aout)
{
    extern __shared__ char smem[];

    const int b     = blockIdx.z;
    const int which = blockIdx.y;
    const int nt    = blockIdx.x;
    const int tid   = threadIdx.x;
    const int w     = tid >> 5;
    const int lane  = tid & 31;
    const int g     = lane >> 2;
    const int tig   = lane & 3;

    const __half* Sh = Shi + ((size_t)(which * BB + b) * 32) * KDIM;
    const __half* Sl = Slo + ((size_t)(which * BB + b) * 32) * KDIM;
    const size_t mbase = ((size_t)(b * NN + nt * 128)) * 4096 + (size_t)which * 2048;
    const __half* mh = mhi + mbase;
    const __half* ml = mlo + mbase;

    GemmCtx cx;
    #pragma unroll
    for (int i = 0; i < 4; i++)
        #pragma unroll
        for (int q = 0; q < 4; q++)
            { cx.acch[i][q] = 0.f; cx.mast[i][q] = 0.f; cx.accm[i][q] = 0.f; }

    const int br = tid >> 3;
    const int bs = tid & 7;

    auto stage = [&](int c, int buf) {
        char* db = smem + buf * STAGE_BYTES;
        __half* Ah = (__half*)(db + AH_OFF);
        __half* Al = (__half*)(db + AL_OFF);
        __half* Bh = (__half*)(db + BH_OFF);
        __half* Bl = (__half*)(db + BL_OFF);
        const int k0 = c * KCHUNK;
        #pragma unroll
        for (int i = 0; i < 4; i++) {
            int slot = tid + 256 * i;
            int r = slot >> 3, s = slot & 7;
            size_t gsrc = (size_t)r * 4096 + k0 + s * 8;
            uint32_t d = (uint32_t)(r * T_STRIDE + s * 8);
            __pipeline_memcpy_async(&Ah[d], &mh[gsrc], 16);
            __pipeline_memcpy_async(&Al[d], &ml[gsrc], 16);
        }
        {
            size_t gsrc = (size_t)br * KDIM + k0 + bs * 8;
            uint32_t d = (uint32_t)(br * T_STRIDE + bs * 8);
            __pipeline_memcpy_async(&Bh[d], &Sh[gsrc], 16);
            __pipeline_memcpy_async(&Bl[d], &Sl[gsrc], 16);
        }
        __pipeline_commit();
    };

    stage(0, 0);

    for (int c = 0; c < NCHUNK; c++) {
        const int buf = c & 1;
        if (c + 1 < NCHUNK) {
            stage(c + 1, buf ^ 1);
            __pipeline_wait_prior(1);
        } else {
            __pipeline_wait_prior(0);
        }
        __syncthreads();
        gemm_compute_chunk(cx, smem + buf * STAGE_BYTES, w, g, tig);
        __syncthreads();
    }

    gemm_epilogue(cx, which ? aout : ain, b, nt, w, g, tig);
}

// ---------------------------------------------------------------------------
// Kernel 2b: step-0 GEMM — stages m from fp32, splits in-register, AND
// writes the split halves to g_mhi/g_mlo for steps 1..4 (replaces msplit).
// Each m element belongs to exactly one (b, nt, which) tile -> written once.
// ---------------------------------------------------------------------------
__global__ void __launch_bounds__(256, 2)
gemm_first_kernel(const float* __restrict__ m,
                  __half* __restrict__ mhi, __half* __restrict__ mlo,
                  const __half* __restrict__ Shi, const __half* __restrict__ Slo,
                  float* __restrict__ ain, float* __restrict__ aout)
{
    extern __shared__ char smem[];

    const int b     = blockIdx.z;
    const int which = blockIdx.y;
    const int nt    = blockIdx.x;
    const int tid   = threadIdx.x;
    const int w     = tid >> 5;
    const int lane  = tid & 31;
    const int g     = lane >> 2;
    const int tig   = lane & 3;

    const __half* Sh = Shi + ((size_t)(which * BB + b) * 32) * KDIM;
    const __half* Sl = Slo + ((size_t)(which * BB + b) * 32) * KDIM;
    const size_t mbase = ((size_t)(b * NN + nt * 128)) * 4096 + (size_t)which * 2048;
    const float* mb = m + mbase;
    __half* outh = mhi + mbase;
    __half* outl = mlo + mbase;

    GemmCtx cx;
    #pragma unroll
    for (int i = 0; i < 4; i++)
        #pragma unroll
        for (int q = 0; q < 4; q++)
            { cx.acch[i][q] = 0.f; cx.mast[i][q] = 0.f; cx.accm[i][q] = 0.f; }

    const int br = tid >> 3;
    const int bs = tid & 7;

    // register prefetch of m chunk (4 slots x 8 floats)
    float4 pf[8];
    auto prefetch_m = [&](int c) {
        const int k0 = c * KCHUNK;
        #pragma unroll
        for (int i = 0; i < 4; i++) {
            int slot = tid + 256 * i;
            int r = slot >> 3, s = slot & 7;
            const float* src = &mb[(size_t)r * 4096 + k0 + s * 8];
            pf[2*i]   = *(const float4*)&src[0];
            pf[2*i+1] = *(const float4*)&src[4];
        }
    };

    prefetch_m(0);

    for (int c = 0; c < NCHUNK; c++) {
        const int buf = c & 1;
        char* db = smem + buf * STAGE_BYTES;
        __half* Ah = (__half*)(db + AH_OFF);
        __half* Al = (__half*)(db + AL_OFF);
        __half* Bh = (__half*)(db + BH_OFF);
        __half* Bl = (__half*)(db + BL_OFF);
        const int k0 = c * KCHUNK;

        // convert prefetched m -> STS + STG
        #pragma unroll
        for (int i = 0; i < 4; i++) {
            int slot = tid + 256 * i;
            int r = slot >> 3, s = slot & 7;
            float xs[8] = {pf[2*i].x, pf[2*i].y, pf[2*i].z, pf[2*i].w,
                           pf[2*i+1].x, pf[2*i+1].y, pf[2*i+1].z, pf[2*i+1].w};
            uint4 hq, lq;
            split8(xs, hq, lq);
            uint32_t d = (uint32_t)(r * T_STRIDE + s * 8);
            *(uint4*)&Ah[d] = hq;
            *(uint4*)&Al[d] = lq;
            size_t gdst = (size_t)r * 4096 + k0 + s * 8;
            *(uint4*)&outh[gdst] = hq;
            *(uint4*)&outl[gdst] = lq;
        }

        // cp.async B tiles
        {
            size_t gsrc = (size_t)br * KDIM + k0 + bs * 8;
            uint32_t d = (uint32_t)(br * T_STRIDE + bs * 8);
            __pipeline_memcpy_async(&Bh[d], &Sh[gsrc], 16);
            __pipeline_memcpy_async(&Bl[d], &Sl[gsrc], 16);
        }
        __pipeline_commit();

        if (c + 1 < NCHUNK) prefetch_m(c + 1);

        __pipeline_wait_prior(0);
        __syncthreads();
        gemm_compute_chunk(cx, db, w, g, tig);
        __syncthreads();
    }

    gemm_epilogue(cx, which ? aout : ain, b, nt, w, g, tig);
}

// ---------------------------------------------------------------------------
// Kernel 3: gates — float4 weights (native [j][k] layout, stride 100:
// 100/4=25 ≡ 1 mod 8 -> conflict-free LDS.128) and float4 cats broadcasts.
// ---------------------------------------------------------------------------
__device__ __forceinline__ float sigmoidf_(float x) {
    return 1.0f / (1.0f + expf(-x));
}

__global__ void __launch_bounds__(256)
gates_kernel(const float* __restrict__ h_in,
             const float* __restrict__ Wz, const float* __restrict__ bz,
             const float* __restrict__ Wr, const float* __restrict__ br,
             const float* __restrict__ Wt, const float* __restrict__ bt,
             const float* __restrict__ ain_, const float* __restrict__ aout_,
             float* __restrict__ hout)
{
    __shared__ float WzT[32][100];   // [j][k] — native Wz layout
    __shared__ float WrT[32][100];
    __shared__ float WtT[32][100];
    __shared__ float cats[8][8][100];

    const int tid = threadIdx.x;
    // 768 float4 slots per matrix
    for (int i = tid; i < 32 * 24; i += 256) {
        int j = i / 24, k4 = i % 24;
        *(float4*)&WzT[j][k4 * 4] = *(const float4*)&Wz[j * 96 + k4 * 4];
        *(float4*)&WrT[j][k4 * 4] = *(const float4*)&Wr[j * 96 + k4 * 4];
        *(float4*)&WtT[j][k4 * 4] = *(const float4*)&Wt[j * 96 + k4 * 4];
    }
    __syncthreads();

    const int w = tid >> 5, lane = tid & 31;
    const int token0 = blockIdx.x * 64 + w * 8;

    float hj[8], az[8], ar[8], at[8];
    float bzv = __ldg(&bz[lane]);
    float brv = __ldg(&br[lane]);
    float btv = __ldg(&bt[lane]);

    #pragma unroll
    for (int t = 0; t < 8; t++) {
        size_t t32 = (size_t)(token0 + t) * 32;
        cats[w][t][lane]      = ain_ [t32 + lane];
        cats[w][t][32 + lane] = aout_[t32 + lane];
        hj[t] = h_in[t32 + lane];
        cats[w][t][64 + lane] = hj[t];
        az[t] = bzv; ar[t] = brv; at[t] = btv;
    }
    __syncwarp();

    // k = 0..63: all three gates
    #pragma unroll 4
    for (int k4 = 0; k4 < 16; k4++) {
        float4 wz = *(const float4*)&WzT[lane][k4 * 4];
        float4 wr = *(const float4*)&WrT[lane][k4 * 4];
        float4 wt = *(const float4*)&WtT[lane][k4 * 4];
        #pragma unroll
        for (int t = 0; t < 8; t++) {
            float4 cv = *(const float4*)&cats[w][t][k4 * 4];
            az[t] += cv.x * wz.x; az[t] += cv.y * wz.y;
            az[t] += cv.z * wz.z; az[t] += cv.w * wz.w;
            ar[t] += cv.x * wr.x; ar[t] += cv.y * wr.y;
            ar[t] += cv.z * wr.z; ar[t] += cv.w * wr.w;
            at[t] += cv.x * wt.x; at[t] += cv.y * wt.y;
            at[t] += cv.z * wt.z; at[t] += cv.w * wt.w;
        }
    }
    // k = 64..95: z, r only
    #pragma unroll 4
    for (int k4 = 16; k4 < 24; k4++) {
        float4 wz = *(const float4*)&WzT[lane][k4 * 4];
        float4 wr = *(const float4*)&WrT[lane][k4 * 4];
        #pragma unroll
        for (int t = 0; t < 8; t++) {
            float4 cv = *(const float4*)&cats[w][t][k4 * 4];
            az[t] += cv.x * wz.x; az[t] += cv.y * wz.y;
            az[t] += cv.z * wz.z; az[t] += cv.w * wz.w;
            ar[t] += cv.x * wr.x; ar[t] += cv.y * wr.y;
            ar[t] += cv.z * wr.z; ar[t] += cv.w * wr.w;
        }
    }

    #pragma unroll
    for (int t = 0; t < 8; t++) {
        float z = sigmoidf_(az[t]);
        float r = sigmoidf_(ar[t]);
        az[t] = z;
        cats[w][t][64 + lane] = r * hj[t];
    }
    __syncwarp();

    // k = 64..95 for t-gate with r*h
    #pragma unroll 4
    for (int k4 = 16; k4 < 24; k4++) {
        float4 wt = *(const float4*)&WtT[lane][k4 * 4];
        #pragma unroll
        for (int t = 0; t < 8; t++) {
            float4 cv = *(const float4*)&cats[w][t][k4 * 4];
            at[t] += cv.x * wt.x; at[t] += cv.y * wt.y;
            at[t] += cv.z * wt.z; at[t] += cv.w * wt.w;
        }
    }

    #pragma unroll
    for (int t = 0; t < 8; t++) {
        float hhat = tanhf(at[t]);
        size_t t32 = (size_t)(token0 + t) * 32;
        hout[t32 + lane] = hj[t] + az[t] * (hhat - hj[t]);
    }
}

// ---------------------------------------------------------------------------
// Kernel 4: final head
// ---------------------------------------------------------------------------
__global__ void __launch_bounds__(512)
final_kernel(const float* __restrict__ hsrc,
             const float* __restrict__ a,
             const float* __restrict__ W1, const float* __restrict__ b1,
             const float* __restrict__ W2, const float* __restrict__ b2,
             float* __restrict__ out)
{
    __shared__ float W1s[33][32];
    __shared__ float hs[16][32];

    const int tid = threadIdx.x;
    for (int i = tid; i < 32 * 33; i += 512) {
        int j = i / 33, k = i % 33;
        W1s[k][j] = W1[i];
    }

    const int w = tid >> 5, lane = tid & 31;
    const int token = blockIdx.x * 16 + w;
    const size_t t32 = (size_t)token * 32;

    hs[w][lane] = hsrc[t32 + lane];
    __syncthreads();

    float acc = __ldg(&b1[lane]);
    #pragma unroll
    for (int k = 0; k < 32; k++)
        acc += hs[w][k] * W1s[k][lane];
    acc += __ldg(&a[token]) * W1s[32][lane];

    float v = tanhf(acc) * __ldg(&W2[lane]);
    #pragma unroll
    for (int off = 16; off > 0; off >>= 1)
        v += __shfl_down_sync(0xFFFFFFFFu, v, off);

    if (lane == 0)
        out[token] = v + __ldg(&b2[0]);
}

// ---------------------------------------------------------------------------
// Launch
// ---------------------------------------------------------------------------
extern "C" void kernel_launch(void* const* d_in, const int* in_sizes, int n_in,
                              void* d_out, int out_size)
{
    const float* x     = (const float*)d_in[0];
    const float* a     = (const float*)d_in[1];
    const float* m     = (const float*)d_in[2];
    const float* W_in  = (const float*)d_in[3];
    const float* b_in  = (const float*)d_in[4];
    const float* W_out = (const float*)d_in[5];
    const float* b_out = (const float*)d_in[6];
    const float* Wz    = (const float*)d_in[7];
    const float* bz    = (const float*)d_in[8];
    const float* Wr    = (const float*)d_in[9];
    const float* br    = (const float*)d_in[10];
    const float* Wt    = (const float*)d_in[11];
    const float* bt    = (const float*)d_in[12];
    const float* W1    = (const float*)d_in[13];
    const float* b1    = (const float*)d_in[14];
    const float* W2    = (const float*)d_in[15];
    const float* b2    = (const float*)d_in[16];
    float* out = (float*)d_out;

    __half *pmhi, *pmlo, *pShi, *pSlo;
    float *pain, *paout, *ph;
    cudaGetSymbolAddress((void**)&pmhi,  g_mhi);
    cudaGetSymbolAddress((void**)&pmlo,  g_mlo);
    cudaGetSymbolAddress((void**)&pShi,  g_Shi);
    cudaGetSymbolAddress((void**)&pSlo,  g_Slo);
    cudaGetSymbolAddress((void**)&pain,  g_ain);
    cudaGetSymbolAddress((void**)&paout, g_aout);
    cudaGetSymbolAddress((void**)&ph,    g_h);

    const int dyn_smem = 2 * STAGE_BYTES;   // 92160
    cudaFuncSetAttribute(gemm_kernel,
                         cudaFuncAttributeMaxDynamicSharedMemorySize, dyn_smem);
    cudaFuncSetAttribute(gemm_first_kernel,
                         cudaFuncAttributeMaxDynamicSharedMemorySize, dyn_smem);

    const int n_tokens = BB * NN;   // 32768

    const float* hsrc = x;
    for (int step = 0; step < NSTEPS; step++) {
        s_kernel<<<n_tokens / 32, 256>>>(hsrc, W_in, b_in, W_out, b_out,
                                         pShi, pSlo);

        dim3 ggrid(4, 2, BB);
        if (step == 0) {
            gemm_first_kernel<<<ggrid, 256, dyn_smem>>>(m, pmhi, pmlo,
                                                        pShi, pSlo, pain, paout);
        } else {
            gemm_kernel<<<ggrid, 256, dyn_smem>>>(pmhi, pmlo, pShi, pSlo,
                                                  pain, paout);
        }

        gates_kernel<<<n_tokens / 64, 256>>>(hsrc, Wz, bz, Wr, br, Wt, bt,
                                             pain, paout, ph);
        hsrc = ph;
    }

    final_kernel<<<n_tokens / 16, 512>>>(hsrc, a, W1, b1, W2, b2, out);
}

// round 13
// speedup vs baseline: 2.2951x; 1.0683x over previous
#include <cuda_runtime.h>
#include <cuda_fp16.h>
#include <cuda_pipeline.h>
#include <math.h>
#include <stdint.h>

#define BB 64
#define NN 512
#define KDIM 2048
#define NSTEPS 5

#define KCHUNK 64
#define NCHUNK (KDIM / KCHUNK)   // 32

#define LO_SCALE     16384.0f            // 2^14
#define LO_INV_SCALE (1.0f / 16384.0f)   // 2^-14

// smem tiles (halves), padded row stride 72 halves (144B = 36 words)
#define T_STRIDE 72
#define AH_OFF 0
#define AL_OFF 18432
#define BH_OFF 36864
#define BL_OFF 41472
#define STAGE_BYTES 46080   // x2 buffers = 92160

// ---------------------------------------------------------------------------
// Scratch
// ---------------------------------------------------------------------------
__device__ __half g_mhi[(size_t)BB * NN * 2 * KDIM];   // 268 MB
__device__ __half g_mlo[(size_t)BB * NN * 2 * KDIM];   // 268 MB (scaled 2^14)
__device__ __half g_Shi[(size_t)2 * BB * 32 * KDIM];   // 16 MB
__device__ __half g_Slo[(size_t)2 * BB * 32 * KDIM];   // 16 MB (scaled 2^14)
__device__ float g_ain [(size_t)BB * NN * 32];
__device__ float g_aout[(size_t)BB * NN * 32];
__device__ float g_h   [(size_t)BB * NN * 32];

// ---------------------------------------------------------------------------
// PTX helpers
// ---------------------------------------------------------------------------
__device__ __forceinline__ uint32_t smem_u32(const void* p) {
    uint32_t a;
    asm("{ .reg .u64 t; cvta.to.shared.u64 t, %1; cvt.u32.u64 %0, t; }"
        : "=r"(a) : "l"(p));
    return a;
}

__device__ __forceinline__ void mma_f16(float* d,
                                        const uint32_t* a,
                                        uint32_t b0, uint32_t b1)
{
    asm volatile(
        "mma.sync.aligned.m16n8k16.row.col.f32.f16.f16.f32 "
        "{%0,%1,%2,%3}, {%4,%5,%6,%7}, {%8,%9}, {%0,%1,%2,%3};"
        : "+f"(d[0]), "+f"(d[1]), "+f"(d[2]), "+f"(d[3])
        : "r"(a[0]), "r"(a[1]), "r"(a[2]), "r"(a[3]), "r"(b0), "r"(b1));
}

__device__ __forceinline__ void ldmx4(uint32_t* r, uint32_t addr) {
    asm volatile(
        "ldmatrix.sync.aligned.m8n8.x4.shared.b16 {%0,%1,%2,%3}, [%4];"
        : "=r"(r[0]), "=r"(r[1]), "=r"(r[2]), "=r"(r[3]) : "r"(addr));
}

// Split x = hi + lo*2^-14, lo stored SCALED to stay in fp16 normal range.
__device__ __forceinline__ void f16_split_scaled(float x, __half& hi, __half& lo) {
    hi = __float2half_rn(x);
    lo = __float2half_rn((x - __half2float(hi)) * LO_SCALE);
}

// split 8 floats into packed hi/lo uint4
__device__ __forceinline__ void split8(const float* xs, uint4& hq, uint4& lq) {
    __half h[8], l[8];
    #pragma unroll
    for (int i = 0; i < 8; i++) f16_split_scaled(xs[i], h[i], l[i]);
    uint32_t hp[4], lp[4];
    #pragma unroll
    for (int q = 0; q < 4; q++) {
        __half2 hh = __halves2half2(h[2*q], h[2*q+1]);
        __half2 ll = __halves2half2(l[2*q], l[2*q+1]);
        hp[q] = *(uint32_t*)&hh;
        lp[q] = *(uint32_t*)&ll;
    }
    hq = make_uint4(hp[0], hp[1], hp[2], hp[3]);
    lq = make_uint4(lp[0], lp[1], lp[2], lp[3]);
}

// ---------------------------------------------------------------------------
// Kernel 1: S projections. 256 blocks x 4 token-groups (W loaded ONCE/block).
// ---------------------------------------------------------------------------
__global__ void __launch_bounds__(256)
s_kernel(const float* __restrict__ h_in,
         const float* __restrict__ W_in,  const float* __restrict__ b_in,
         const float* __restrict__ W_out, const float* __restrict__ b_out,
         __half* __restrict__ Shi, __half* __restrict__ Slo)
{
    __shared__ float Ws[2][128][32];
    __shared__ float hs[32][36];

    const int tid = threadIdx.x;
    for (int i = tid; i < 128 * 32; i += 256) {
        Ws[0][i >> 5][i & 31] = W_in[i];
        Ws[1][i >> 5][i & 31] = W_out[i];
    }

    const int w = tid >> 5, lane = tid & 31;

    for (int it = 0; it < 4; it++) {
        const int token0 = blockIdx.x * 128 + it * 32;

        __syncthreads();   // previous iteration's hs reads done / Ws ready
        {
            int r = tid >> 3, c = (tid & 7) * 4;
            *(float4*)&hs[r][c] =
                *(const float4*)&h_in[(size_t)(token0 + r) * 32 + c];
        }
        __syncthreads();

        float hreg[32];
        #pragma unroll
        for (int k = 0; k < 32; k++) hreg[k] = hs[lane][k];

        const int b = token0 >> 9;
        const int n = (token0 & 511) + lane;

        #pragma unroll
        for (int which = 0; which < 2; which++) {
            const float* bias = which ? b_out : b_in;
            #pragma unroll
            for (int jj = 0; jj < 16; jj++) {
                int j = w * 16 + jj;
                float acc = __ldg(&bias[j]);
                #pragma unroll
                for (int k4 = 0; k4 < 8; k4++) {
                    float4 wv = *(const float4*)&Ws[which][j][k4 * 4];
                    acc += hreg[k4*4+0] * wv.x;
                    acc += hreg[k4*4+1] * wv.y;
                    acc += hreg[k4*4+2] * wv.z;
                    acc += hreg[k4*4+3] * wv.w;
                }
                __half hi, lo;
                f16_split_scaled(acc, hi, lo);
                int hp = j >> 2, e = j & 3;
                size_t idx = (((size_t)which * BB + b) * 32 + hp) * KDIM
                             + e * 512 + n;
                Shi[idx] = hi;
                Slo[idx] = lo;
            }
        }
    }
}

// ---------------------------------------------------------------------------
// Shared GEMM compute body — ldmatrix fragment loads (24 instr vs 96 LDS.32)
// ---------------------------------------------------------------------------
struct GemmCtx {
    float acch[4][4], mast[4][4], accm[4][4];
};

__device__ __forceinline__ void gemm_compute_chunk(
    GemmCtx& cx, char* db, int w, int lane)
{
    const uint32_t base = smem_u32(db);
    // A: lane -> row 16w + (lane&15), col (lane>>4)*8   (halves), x2 bytes
    const uint32_t aoff =
        (uint32_t)(((16 * w + (lane & 15)) * T_STRIDE + ((lane >> 4) << 3)) * 2);
    const uint32_t ah_b = base + AH_OFF + aoff;
    const uint32_t al_b = base + AL_OFF + aoff;
    // B: lane -> row (lane>>4)*8 + (lane&7), col ((lane>>3)&1)*8
    const uint32_t boff =
        (uint32_t)(((((lane >> 4) << 3) + (lane & 7)) * T_STRIDE
                    + (((lane >> 3) & 1) << 3)) * 2);
    const uint32_t bh_b = base + BH_OFF + boff;
    const uint32_t bl_b = base + BL_OFF + boff;
    const uint32_t PSTEP = 16 * T_STRIDE * 2;   // +16 B-rows

    #pragma unroll
    for (int ks = 0; ks < 4; ks++) {
        const uint32_t ksb = ks * 32;   // 16 halves = 32 bytes
        uint32_t ah[4], al[4];
        ldmx4(ah, ah_b + ksb);
        ldmx4(al, al_b + ksb);

        #pragma unroll
        for (int p = 0; p < 2; p++) {
            uint32_t bh[4], bl[4];
            ldmx4(bh, bh_b + ksb + p * PSTEP);
            ldmx4(bl, bl_b + ksb + p * PSTEP);
            // bh[0],bh[1] = b0,b1 for n2=2p ; bh[2],bh[3] for n2=2p+1
            mma_f16(cx.acch[2*p],   ah, bh[0], bh[1]);
            mma_f16(cx.accm[2*p],   ah, bl[0], bl[1]);
            mma_f16(cx.accm[2*p],   al, bh[0], bh[1]);
            mma_f16(cx.acch[2*p+1], ah, bh[2], bh[3]);
            mma_f16(cx.accm[2*p+1], ah, bl[2], bl[3]);
            mma_f16(cx.accm[2*p+1], al, bh[2], bh[3]);
        }
    }
    // PROMOTE
    #pragma unroll
    for (int n2 = 0; n2 < 4; n2++)
        #pragma unroll
        for (int q = 0; q < 4; q++) {
            cx.mast[n2][q] += cx.acch[n2][q];
            cx.acch[n2][q] = 0.f;
        }
}

__device__ __forceinline__ void gemm_epilogue(
    GemmCtx& cx, float* outp, int b, int nt, int w, int g, int tig)
{
    const int row0 = nt * 128 + 16 * w + g;
    #pragma unroll
    for (int n2 = 0; n2 < 4; n2++) {
        int col = n2 * 8 + tig * 2;
        float v0 = cx.mast[n2][0] + cx.accm[n2][0] * LO_INV_SCALE;
        float v1 = cx.mast[n2][1] + cx.accm[n2][1] * LO_INV_SCALE;
        float v2 = cx.mast[n2][2] + cx.accm[n2][2] * LO_INV_SCALE;
        float v3 = cx.mast[n2][3] + cx.accm[n2][3] * LO_INV_SCALE;
        *(float2*)&outp[((size_t)(b * NN + row0))     * 32 + col] = make_float2(v0, v1);
        *(float2*)&outp[((size_t)(b * NN + row0 + 8)) * 32 + col] = make_float2(v2, v3);
    }
}

// ---------------------------------------------------------------------------
// Kernel 2a: steady-state GEMM (steps 1..4), pure cp.async staging.
// ---------------------------------------------------------------------------
__global__ void __launch_bounds__(256, 2)
gemm_kernel(const __half* __restrict__ mhi, const __half* __restrict__ mlo,
            const __half* __restrict__ Shi, const __half* __restrict__ Slo,
            float* __restrict__ ain, float* __restrict__ aout)
{
    extern __shared__ char smem[];

    const int b     = blockIdx.z;
    const int which = blockIdx.y;
    const int nt    = blockIdx.x;
    const int tid   = threadIdx.x;
    const int w     = tid >> 5;
    const int lane  = tid & 31;
    const int g     = lane >> 2;
    const int tig   = lane & 3;

    const __half* Sh = Shi + ((size_t)(which * BB + b) * 32) * KDIM;
    const __half* Sl = Slo + ((size_t)(which * BB + b) * 32) * KDIM;
    const size_t mbase = ((size_t)(b * NN + nt * 128)) * 4096 + (size_t)which * 2048;
    const __half* mh = mhi + mbase;
    const __half* ml = mlo + mbase;

    GemmCtx cx;
    #pragma unroll
    for (int i = 0; i < 4; i++)
        #pragma unroll
        for (int q = 0; q < 4; q++)
            { cx.acch[i][q] = 0.f; cx.mast[i][q] = 0.f; cx.accm[i][q] = 0.f; }

    const int br = tid >> 3;
    const int bs = tid & 7;

    auto stage = [&](int c, int buf) {
        char* db = smem + buf * STAGE_BYTES;
        __half* Ah = (__half*)(db + AH_OFF);
        __half* Al = (__half*)(db + AL_OFF);
        __half* Bh = (__half*)(db + BH_OFF);
        __half* Bl = (__half*)(db + BL_OFF);
        const int k0 = c * KCHUNK;
        #pragma unroll
        for (int i = 0; i < 4; i++) {
            int slot = tid + 256 * i;
            int r = slot >> 3, s = slot & 7;
            size_t gsrc = (size_t)r * 4096 + k0 + s * 8;
            uint32_t d = (uint32_t)(r * T_STRIDE + s * 8);
            __pipeline_memcpy_async(&Ah[d], &mh[gsrc], 16);
            __pipeline_memcpy_async(&Al[d], &ml[gsrc], 16);
        }
        {
            size_t gsrc = (size_t)br * KDIM + k0 + bs * 8;
            uint32_t d = (uint32_t)(br * T_STRIDE + bs * 8);
            __pipeline_memcpy_async(&Bh[d], &Sh[gsrc], 16);
            __pipeline_memcpy_async(&Bl[d], &Sl[gsrc], 16);
        }
        __pipeline_commit();
    };

    stage(0, 0);

    for (int c = 0; c < NCHUNK; c++) {
        const int buf = c & 1;
        if (c + 1 < NCHUNK) {
            stage(c + 1, buf ^ 1);
            __pipeline_wait_prior(1);
        } else {
            __pipeline_wait_prior(0);
        }
        __syncthreads();
        gemm_compute_chunk(cx, smem + buf * STAGE_BYTES, w, lane);
        __syncthreads();
    }

    gemm_epilogue(cx, which ? aout : ain, b, nt, w, g, tig);
}

// ---------------------------------------------------------------------------
// Kernel 2b: step-0 GEMM — stages m from fp32, splits in-register, AND
// writes the split halves to g_mhi/g_mlo for steps 1..4.
// ---------------------------------------------------------------------------
__global__ void __launch_bounds__(256, 2)
gemm_first_kernel(const float* __restrict__ m,
                  __half* __restrict__ mhi, __half* __restrict__ mlo,
                  const __half* __restrict__ Shi, const __half* __restrict__ Slo,
                  float* __restrict__ ain, float* __restrict__ aout)
{
    extern __shared__ char smem[];

    const int b     = blockIdx.z;
    const int which = blockIdx.y;
    const int nt    = blockIdx.x;
    const int tid   = threadIdx.x;
    const int w     = tid >> 5;
    const int lane  = tid & 31;
    const int g     = lane >> 2;
    const int tig   = lane & 3;

    const __half* Sh = Shi + ((size_t)(which * BB + b) * 32) * KDIM;
    const __half* Sl = Slo + ((size_t)(which * BB + b) * 32) * KDIM;
    const size_t mbase = ((size_t)(b * NN + nt * 128)) * 4096 + (size_t)which * 2048;
    const float* mb = m + mbase;
    __half* outh = mhi + mbase;
    __half* outl = mlo + mbase;

    GemmCtx cx;
    #pragma unroll
    for (int i = 0; i < 4; i++)
        #pragma unroll
        for (int q = 0; q < 4; q++)
            { cx.acch[i][q] = 0.f; cx.mast[i][q] = 0.f; cx.accm[i][q] = 0.f; }

    const int br = tid >> 3;
    const int bs = tid & 7;

    float4 pf[8];
    auto prefetch_m = [&](int c) {
        const int k0 = c * KCHUNK;
        #pragma unroll
        for (int i = 0; i < 4; i++) {
            int slot = tid + 256 * i;
            int r = slot >> 3, s = slot & 7;
            const float* src = &mb[(size_t)r * 4096 + k0 + s * 8];
            pf[2*i]   = *(const float4*)&src[0];
            pf[2*i+1] = *(const float4*)&src[4];
        }
    };

    prefetch_m(0);

    for (int c = 0; c < NCHUNK; c++) {
        const int buf = c & 1;
        char* db = smem + buf * STAGE_BYTES;
        __half* Ah = (__half*)(db + AH_OFF);
        __half* Al = (__half*)(db + AL_OFF);
        __half* Bh = (__half*)(db + BH_OFF);
        __half* Bl = (__half*)(db + BL_OFF);
        const int k0 = c * KCHUNK;

        #pragma unroll
        for (int i = 0; i < 4; i++) {
            int slot = tid + 256 * i;
            int r = slot >> 3, s = slot & 7;
            float xs[8] = {pf[2*i].x, pf[2*i].y, pf[2*i].z, pf[2*i].w,
                           pf[2*i+1].x, pf[2*i+1].y, pf[2*i+1].z, pf[2*i+1].w};
            uint4 hq, lq;
            split8(xs, hq, lq);
            uint32_t d = (uint32_t)(r * T_STRIDE + s * 8);
            *(uint4*)&Ah[d] = hq;
            *(uint4*)&Al[d] = lq;
            size_t gdst = (size_t)r * 4096 + k0 + s * 8;
            *(uint4*)&outh[gdst] = hq;
            *(uint4*)&outl[gdst] = lq;
        }

        {
            size_t gsrc = (size_t)br * KDIM + k0 + bs * 8;
            uint32_t d = (uint32_t)(br * T_STRIDE + bs * 8);
            __pipeline_memcpy_async(&Bh[d], &Sh[gsrc], 16);
            __pipeline_memcpy_async(&Bl[d], &Sl[gsrc], 16);
        }
        __pipeline_commit();

        if (c + 1 < NCHUNK) prefetch_m(c + 1);

        __pipeline_wait_prior(0);
        __syncthreads();
        gemm_compute_chunk(cx, db, w, lane);
        __syncthreads();
    }

    gemm_epilogue(cx, which ? aout : ain, b, nt, w, g, tig);
}

// ---------------------------------------------------------------------------
// Kernel 3: gates — float4 weights (native [j][k] layout, stride 100)
// ---------------------------------------------------------------------------
__device__ __forceinline__ float sigmoidf_(float x) {
    return 1.0f / (1.0f + expf(-x));
}

__global__ void __launch_bounds__(256)
gates_kernel(const float* __restrict__ h_in,
             const float* __restrict__ Wz, const float* __restrict__ bz,
             const float* __restrict__ Wr, const float* __restrict__ br,
             const float* __restrict__ Wt, const float* __restrict__ bt,
             const float* __restrict__ ain_, const float* __restrict__ aout_,
             float* __restrict__ hout)
{
    __shared__ float WzT[32][100];
    __shared__ float WrT[32][100];
    __shared__ float WtT[32][100];
    __shared__ float cats[8][8][100];

    const int tid = threadIdx.x;
    for (int i = tid; i < 32 * 24; i += 256) {
        int j = i / 24, k4 = i % 24;
        *(float4*)&WzT[j][k4 * 4] = *(const float4*)&Wz[j * 96 + k4 * 4];
        *(float4*)&WrT[j][k4 * 4] = *(const float4*)&Wr[j * 96 + k4 * 4];
        *(float4*)&WtT[j][k4 * 4] = *(const float4*)&Wt[j * 96 + k4 * 4];
    }
    __syncthreads();

    const int w = tid >> 5, lane = tid & 31;
    const int token0 = blockIdx.x * 64 + w * 8;

    float hj[8], az[8], ar[8], at[8];
    float bzv = __ldg(&bz[lane]);
    float brv = __ldg(&br[lane]);
    float btv = __ldg(&bt[lane]);

    #pragma unroll
    for (int t = 0; t < 8; t++) {
        size_t t32 = (size_t)(token0 + t) * 32;
        cats[w][t][lane]      = ain_ [t32 + lane];
        cats[w][t][32 + lane] = aout_[t32 + lane];
        hj[t] = h_in[t32 + lane];
        cats[w][t][64 + lane] = hj[t];
        az[t] = bzv; ar[t] = brv; at[t] = btv;
    }
    __syncwarp();

    #pragma unroll 4
    for (int k4 = 0; k4 < 16; k4++) {
        float4 wz = *(const float4*)&WzT[lane][k4 * 4];
        float4 wr = *(const float4*)&WrT[lane][k4 * 4];
        float4 wt = *(const float4*)&WtT[lane][k4 * 4];
        #pragma unroll
        for (int t = 0; t < 8; t++) {
            float4 cv = *(const float4*)&cats[w][t][k4 * 4];
            az[t] += cv.x * wz.x; az[t] += cv.y * wz.y;
            az[t] += cv.z * wz.z; az[t] += cv.w * wz.w;
            ar[t] += cv.x * wr.x; ar[t] += cv.y * wr.y;
            ar[t] += cv.z * wr.z; ar[t] += cv.w * wr.w;
            at[t] += cv.x * wt.x; at[t] += cv.y * wt.y;
            at[t] += cv.z * wt.z; at[t] += cv.w * wt.w;
        }
    }
    #pragma unroll 4
    for (int k4 = 16; k4 < 24; k4++) {
        float4 wz = *(const float4*)&WzT[lane][k4 * 4];
        float4 wr = *(const float4*)&WrT[lane][k4 * 4];
        #pragma unroll
        for (int t = 0; t < 8; t++) {
            float4 cv = *(const float4*)&cats[w][t][k4 * 4];
            az[t] += cv.x * wz.x; az[t] += cv.y * wz.y;
            az[t] += cv.z * wz.z; az[t] += cv.w * wz.w;
            ar[t] += cv.x * wr.x; ar[t] += cv.y * wr.y;
            ar[t] += cv.z * wr.z; ar[t] += cv.w * wr.w;
        }
    }

    #pragma unroll
    for (int t = 0; t < 8; t++) {
        float z = sigmoidf_(az[t]);
        float r = sigmoidf_(ar[t]);
        az[t] = z;
        cats[w][t][64 + lane] = r * hj[t];
    }
    __syncwarp();

    #pragma unroll 4
    for (int k4 = 16; k4 < 24; k4++) {
        float4 wt = *(const float4*)&WtT[lane][k4 * 4];
        #pragma unroll
        for (int t = 0; t < 8; t++) {
            float4 cv = *(const float4*)&cats[w][t][k4 * 4];
            at[t] += cv.x * wt.x; at[t] += cv.y * wt.y;
            at[t] += cv.z * wt.z; at[t] += cv.w * wt.w;
        }
    }

    #pragma unroll
    for (int t = 0; t < 8; t++) {
        float hhat = tanhf(at[t]);
        size_t t32 = (size_t)(token0 + t) * 32;
        hout[t32 + lane] = hj[t] + az[t] * (hhat - hj[t]);
    }
}

// ---------------------------------------------------------------------------
// Kernel 4: final head
// ---------------------------------------------------------------------------
__global__ void __launch_bounds__(512)
final_kernel(const float* __restrict__ hsrc,
             const float* __restrict__ a,
             const float* __restrict__ W1, const float* __restrict__ b1,
             const float* __restrict__ W2, const float* __restrict__ b2,
             float* __restrict__ out)
{
    __shared__ float W1s[33][32];
    __shared__ float hs[16][32];

    const int tid = threadIdx.x;
    for (int i = tid; i < 32 * 33; i += 512) {
        int j = i / 33, k = i % 33;
        W1s[k][j] = W1[i];
    }

    const int w = tid >> 5, lane = tid & 31;
    const int token = blockIdx.x * 16 + w;
    const size_t t32 = (size_t)token * 32;

    hs[w][lane] = hsrc[t32 + lane];
    __syncthreads();

    float acc = __ldg(&b1[lane]);
    #pragma unroll
    for (int k = 0; k < 32; k++)
        acc += hs[w][k] * W1s[k][lane];
    acc += __ldg(&a[token]) * W1s[32][lane];

    float v = tanhf(acc) * __ldg(&W2[lane]);
    #pragma unroll
    for (int off = 16; off > 0; off >>= 1)
        v += __shfl_down_sync(0xFFFFFFFFu, v, off);

    if (lane == 0)
        out[token] = v + __ldg(&b2[0]);
}

// ---------------------------------------------------------------------------
// Launch
// ---------------------------------------------------------------------------
extern "C" void kernel_launch(void* const* d_in, const int* in_sizes, int n_in,
                              void* d_out, int out_size)
{
    const float* x     = (const float*)d_in[0];
    const float* a     = (const float*)d_in[1];
    const float* m     = (const float*)d_in[2];
    const float* W_in  = (const float*)d_in[3];
    const float* b_in  = (const float*)d_in[4];
    const float* W_out = (const float*)d_in[5];
    const float* b_out = (const float*)d_in[6];
    const float* Wz    = (const float*)d_in[7];
    const float* bz    = (const float*)d_in[8];
    const float* Wr    = (const float*)d_in[9];
    const float* br    = (const float*)d_in[10];
    const float* Wt    = (const float*)d_in[11];
    const float* bt    = (const float*)d_in[12];
    const float* W1    = (const float*)d_in[13];
    const float* b1    = (const float*)d_in[14];
    const float* W2    = (const float*)d_in[15];
    const float* b2    = (const float*)d_in[16];
    float* out = (float*)d_out;

    __half *pmhi, *pmlo, *pShi, *pSlo;
    float *pain, *paout, *ph;
    cudaGetSymbolAddress((void**)&pmhi,  g_mhi);
    cudaGetSymbolAddress((void**)&pmlo,  g_mlo);
    cudaGetSymbolAddress((void**)&pShi,  g_Shi);
    cudaGetSymbolAddress((void**)&pSlo,  g_Slo);
    cudaGetSymbolAddress((void**)&pain,  g_ain);
    cudaGetSymbolAddress((void**)&paout, g_aout);
    cudaGetSymbolAddress((void**)&ph,    g_h);

    const int dyn_smem = 2 * STAGE_BYTES;   // 92160
    cudaFuncSetAttribute(gemm_kernel,
                         cudaFuncAttributeMaxDynamicSharedMemorySize, dyn_smem);
    cudaFuncSetAttribute(gemm_first_kernel,
                         cudaFuncAttributeMaxDynamicSharedMemorySize, dyn_smem);

    const int n_tokens = BB * NN;   // 32768

    const float* hsrc = x;
    for (int step = 0; step < NSTEPS; step++) {
        s_kernel<<<n_tokens / 128, 256>>>(hsrc, W_in, b_in, W_out, b_out,
                                          pShi, pSlo);

        dim3 ggrid(4, 2, BB);
        if (step == 0) {
            gemm_first_kernel<<<ggrid, 256, dyn_smem>>>(m, pmhi, pmlo,
                                                        pShi, pSlo, pain, paout);
        } else {
            gemm_kernel<<<ggrid, 256, dyn_smem>>>(pmhi, pmlo, pShi, pSlo,
                                                  pain, paout);
        }

        gates_kernel<<<n_tokens / 64, 256>>>(hsrc, Wz, bz, Wr, br, Wt, bt,
                                             pain, paout, ph);
        hsrc = ph;
    }

    final_kernel<<<n_tokens / 16, 512>>>(hsrc, a, W1, b1, W2, b2, out);
}